// round 12
// baseline (speedup 1.0000x reference)
#include <cuda_runtime.h>
#include <cuda_bf16.h>
#include <stdint.h>
#include <math.h>

#define NN   100000
#define NE   1600000
#define CIN  128
#define CHID 256
#define COUT 40
#define P3W  80          // layer-3 pre-agg width (40 self + 40 agg-input)

typedef __nv_bfloat16  bf16;
typedef __nv_bfloat162 bf162;

#define SCAN_T  1024
#define SCAN_NB ((NN + SCAN_T - 1) / SCAN_T)   // 98

// ---------------- device scratch ----------------
__device__ int   g_deg[NN];
__device__ int   g_rowptr[NN + 1];
__device__ int   g_cursor[NN];
__device__ int   g_bsums[SCAN_NB];
__device__ int2  g_cpack[NE];          // (src, weight bits)

__device__ bf16  g_xhi[(size_t)NN * CIN];
__device__ bf16  g_xlo[(size_t)NN * CIN];
__device__ bf16  g_h1hi[(size_t)NN * CHID];
__device__ bf16  g_h1lo[(size_t)NN * CHID];
__device__ bf16  g_h2hi[(size_t)NN * CHID];
__device__ bf16  g_h2lo[(size_t)NN * CHID];
__device__ bf16  g_aghi[(size_t)NN * CHID];
__device__ bf16  g_aglo[(size_t)NN * CHID];

__device__ bf16  g_w1hi[CHID * 2 * CIN];
__device__ bf16  g_w1lo[CHID * 2 * CIN];
__device__ bf16  g_w2hi[CHID * 2 * CHID];
__device__ bf16  g_w2lo[CHID * 2 * CHID];
__device__ bf16  g_w3hi[P3W * CHID];          // [80][256], k-contiguous (K2=256)
__device__ bf16  g_w3lo[P3W * CHID];

__device__ float g_p3[(size_t)NN * P3W];

// ---------------- helpers ----------------
__device__ __forceinline__ void fsplit(float v, bf16 &hi, bf16 &lo) {
    hi = __float2bfloat16(v);
    lo = __float2bfloat16(v - __bfloat162float(hi));
}

__device__ __forceinline__ void mma16816(float *c, const uint32_t *a, const uint32_t *b) {
    asm volatile(
        "mma.sync.aligned.m16n8k16.row.col.f32.bf16.bf16.f32 "
        "{%0,%1,%2,%3}, {%4,%5,%6,%7}, {%8,%9}, {%0,%1,%2,%3};\n"
        : "+f"(c[0]), "+f"(c[1]), "+f"(c[2]), "+f"(c[3])
        : "r"(a[0]), "r"(a[1]), "r"(a[2]), "r"(a[3]), "r"(b[0]), "r"(b[1]));
}

__device__ __forceinline__ void ldsm_x4(uint32_t *r, uint32_t a) {
    asm volatile("ldmatrix.sync.aligned.m8n8.x4.shared.b16 {%0,%1,%2,%3}, [%4];"
                 : "=r"(r[0]), "=r"(r[1]), "=r"(r[2]), "=r"(r[3]) : "r"(a));
}
__device__ __forceinline__ void ldsm_x2(uint32_t *r, uint32_t a) {
    asm volatile("ldmatrix.sync.aligned.m8n8.x2.shared.b16 {%0,%1}, [%2];"
                 : "=r"(r[0]), "=r"(r[1]) : "r"(a));
}

__device__ __forceinline__ void cp_async16(uint32_t d, const void *s, bool p) {
    asm volatile("cp.async.cg.shared.global [%0], [%1], 16, %2;\n"
                 :: "r"(d), "l"(s), "r"(p ? 16 : 0));
}
__device__ __forceinline__ void cp_commit() { asm volatile("cp.async.commit_group;\n"); }
template <int N> __device__ __forceinline__ void cp_wait() {
    asm volatile("cp.async.wait_group %0;\n" :: "n"(N));
}

// 16B-granular XOR swizzle on 32B rows: conflict-free for both cp.async stores
// and ldmatrix phases.  sw(row, half) = row*32 + ((half ^ ((row>>2)&1)) << 4)
__device__ __forceinline__ uint32_t sw_off(int row, int half) {
    return (uint32_t)(row * 32 + ((half ^ ((row >> 2) & 1)) << 4));
}

// ---------------- CSR build ----------------
__global__ void k_zero_deg() {
    int i = blockIdx.x * blockDim.x + threadIdx.x;
    if (i < NN) g_deg[i] = 0;
}

__global__ void k_hist(const int *__restrict__ dst) {
    int e = blockIdx.x * blockDim.x + threadIdx.x;
    if (e < NE) atomicAdd(&g_deg[dst[e]], 1);
}

__global__ void k_scan1() {
    __shared__ int s[SCAN_T];
    int t = threadIdx.x;
    int g = blockIdx.x * SCAN_T + t;
    int v = (g < NN) ? g_deg[g] : 0;
    s[t] = v;
    __syncthreads();
    for (int o = 1; o < SCAN_T; o <<= 1) {
        int x = (t >= o) ? s[t - o] : 0;
        __syncthreads();
        s[t] += x;
        __syncthreads();
    }
    if (g < NN) g_rowptr[g + 1] = s[t];
    if (t == SCAN_T - 1) g_bsums[blockIdx.x] = s[t];
}

__global__ void k_scan2() {
    __shared__ int s[128];
    int t = threadIdx.x;
    int v = (t < SCAN_NB) ? g_bsums[t] : 0;
    s[t] = v;
    __syncthreads();
    for (int o = 1; o < 128; o <<= 1) {
        int x = (t >= o) ? s[t - o] : 0;
        __syncthreads();
        s[t] += x;
        __syncthreads();
    }
    if (t < SCAN_NB) g_bsums[t] = s[t] - v;
}

__global__ void k_scan3() {
    int g = blockIdx.x * SCAN_T + threadIdx.x;
    if (g < NN) {
        int v = g_rowptr[g + 1] + g_bsums[blockIdx.x];
        g_rowptr[g + 1] = v;
        g_cursor[g] = v - g_deg[g];
    }
    if (g == 0) g_rowptr[0] = 0;
}

__global__ void k_fill(const int *__restrict__ src, const int *__restrict__ dst,
                       const float *__restrict__ ew) {
    int e = blockIdx.x * blockDim.x + threadIdx.x;
    if (e < NE) {
        int d = dst[e];
        int p = atomicAdd(&g_cursor[d], 1);
        g_cpack[p] = make_int2(src[e], __float_as_int(ew[e]));
    }
}

// ---------------- conversions ----------------
__global__ void k_split(const float *__restrict__ in, bf16 *__restrict__ hi,
                        bf16 *__restrict__ lo, int n) {
    int i = blockIdx.x * blockDim.x + threadIdx.x;
    if (i < n) fsplit(in[i], hi[i], lo[i]);
}

__global__ void k_convW(const float *__restrict__ W, bf16 *__restrict__ whi,
                        bf16 *__restrict__ wlo, int K2, int M) {
    int i = blockIdx.x * blockDim.x + threadIdx.x;
    if (i < K2 * M) {
        int n = i / K2;
        int k = i - n * K2;
        fsplit(W[(size_t)k * M + n], whi[i], wlo[i]);
    }
}

// W3 [512][40] fp32 -> B3 [80][256] bf16 hi/lo, k-contiguous with stride CHID=256.
__global__ void k_convW3(const float *__restrict__ W3) {
    int i = blockIdx.x * blockDim.x + threadIdx.x;
    if (i < P3W * CHID) {
        int n = i / CHID;
        int k = i - n * CHID;
        float v = (n < COUT) ? W3[(size_t)k * COUT + n]
                             : W3[(size_t)(CHID + k) * COUT + (n - COUT)];
        fsplit(v, g_w3hi[i], g_w3lo[i]);
    }
}

// ---------------- aggregation (CSR, no atomics) ----------------
union U4 { uint2 u; bf16 b[4]; };
union U8 { uint4 u; bf16 b[8]; };

__global__ void k_agg128(const float *__restrict__ x) {
    int lane = threadIdx.x & 31, w = threadIdx.x >> 5;
    int node = blockIdx.x * 8 + w;
    if (node >= NN) return;
    int e0 = g_rowptr[node], e1 = g_rowptr[node + 1];
    float a0 = 0.f, a1 = 0.f, a2 = 0.f, a3 = 0.f;
    for (int e = e0; e < e1; e++) {
        int2  pk = g_cpack[e];
        float wt = __int_as_float(pk.y);
        float4 v = *(const float4 *)(x + (size_t)pk.x * CIN + lane * 4);
        a0 += wt * v.x; a1 += wt * v.y; a2 += wt * v.z; a3 += wt * v.w;
    }
    U4 oh, ol;
    fsplit(a0, oh.b[0], ol.b[0]);
    fsplit(a1, oh.b[1], ol.b[1]);
    fsplit(a2, oh.b[2], ol.b[2]);
    fsplit(a3, oh.b[3], ol.b[3]);
    size_t off = (size_t)node * CIN + lane * 4;
    *(uint2 *)(g_aghi + off) = oh.u;
    *(uint2 *)(g_aglo + off) = ol.u;
}

__global__ void k_agg256(const bf16 *__restrict__ hhi, const bf16 *__restrict__ hlo) {
    int lane = threadIdx.x & 31, w = threadIdx.x >> 5;
    int node = blockIdx.x * 8 + w;
    if (node >= NN) return;
    int e0 = g_rowptr[node], e1 = g_rowptr[node + 1];
    float acc[8];
#pragma unroll
    for (int j = 0; j < 8; j++) acc[j] = 0.f;
    for (int e = e0; e < e1; e++) {
        int2  pk = g_cpack[e];
        float wt = __int_as_float(pk.y);
        uint4 uh = *(const uint4 *)(hhi + (size_t)pk.x * CHID + lane * 8);
        uint4 ul = *(const uint4 *)(hlo + (size_t)pk.x * CHID + lane * 8);
        const bf162 *ph = (const bf162 *)&uh;
        const bf162 *pl = (const bf162 *)&ul;
#pragma unroll
        for (int j = 0; j < 4; j++) {
            float2 fh = __bfloat1622float2(ph[j]);
            float2 fl = __bfloat1622float2(pl[j]);
            acc[2 * j]     += wt * (fh.x + fl.x);
            acc[2 * j + 1] += wt * (fh.y + fl.y);
        }
    }
    U8 oh, ol;
#pragma unroll
    for (int j = 0; j < 8; j++) fsplit(acc[j], oh.b[j], ol.b[j]);
    size_t off = (size_t)node * CHID + lane * 8;
    *(uint4 *)(g_aghi + off) = oh.u;
    *(uint4 *)(g_aglo + off) = ol.u;
}

// ---------------- GEMM: 128 x (32*NT) block tile, 8 warps, 3-stage cp.async ----------------
// A0/A1: hi/lo bf16 [N, KPART] (two k-parts). B: hi/lo bf16 [NOUT][K2].
// Split product: C = Ahi*Bhi + Ahi*Blo + Alo*Bhi  (fp32 accum)
// Fragments via ldmatrix on swizzled smem; dynamic smem (3 stages).
// B staging strides rows by 128 so BN > 128 tiles are fully covered
// (round-11 bug: rows 128..255 were never staged).
#define STAGES 3

template <int K2, int KPART, int NOUT, int NT, bool SPLIT>
__global__ __launch_bounds__(256) void k_gemm(
    const bf16 *__restrict__ Ah0, const bf16 *__restrict__ Al0,
    const bf16 *__restrict__ Ah1, const bf16 *__restrict__ Al1,
    const bf16 *__restrict__ Bh, const bf16 *__restrict__ Bl,
    const float *__restrict__ bias,
    bf16 *__restrict__ Chi, bf16 *__restrict__ Clo, float *__restrict__ Cf) {

    constexpr int BN = 32 * NT;
    constexpr int STAGE_ELEMS = 2 * (128 + BN) * 16;   // bf16 elems per stage
    extern __shared__ bf16 sm[];                        // [STAGES][STAGE_ELEMS]

    int tid = threadIdx.x, lane = tid & 31, warp = tid >> 5;
    int wm = warp >> 2, wn = warp & 3;            // 2 x 4 warp grid
    int rb = blockIdx.x, cb = blockIdx.y;

    const int KT = K2 / 16;

    float acc[4][NT][4];
#pragma unroll
    for (int a = 0; a < 4; a++)
#pragma unroll
        for (int b = 0; b < NT; b++)
#pragma unroll
            for (int c = 0; c < 4; c++) acc[a][b][c] = 0.f;

    // staging: thread t covers (row = t>>1, half = t&1); B rows strided by 128
    int sr = tid >> 1, sh = tid & 1;
    int a_gr = rb * 128 + sr;
    bool a_ok = a_gr < NN;
    int a_grc = a_ok ? a_gr : 0;
    uint32_t st_off = sw_off(sr, sh);             // swizzled 16B-chunk offset (A)

    auto issue = [&](int kt, int buf) {
        int part = (kt * 16 >= KPART) ? 1 : 0;
        int kcol = kt * 16 - part * KPART;
        const bf16 *Ah = part ? Ah1 : Ah0;
        const bf16 *Al = part ? Al1 : Al0;
        uint32_t base = (uint32_t)__cvta_generic_to_shared(sm + buf * STAGE_ELEMS);
        cp_async16(base + st_off,        Ah + (size_t)a_grc * KPART + kcol + sh * 8, a_ok);
        cp_async16(base + 4096 + st_off, Al + (size_t)a_grc * KPART + kcol + sh * 8, a_ok);
#pragma unroll
        for (int r = sr; r < BN; r += 128) {
            int  gn = cb * BN + r;
            bool ok = gn < NOUT;
            int  gnc = ok ? gn : 0;
            uint32_t so = sw_off(r, sh);
            cp_async16(base + 8192 + so,
                       Bh + (size_t)gnc * K2 + kt * 16 + sh * 8, ok);
            cp_async16(base + 8192 + BN * 32 + so,
                       Bl + (size_t)gnc * K2 + kt * 16 + sh * 8, ok);
        }
    };

#pragma unroll
    for (int s = 0; s < STAGES - 1; s++) {
        issue(s, s);
        cp_commit();
    }

    // per-lane ldmatrix address offsets (swizzle bit is lane-constant because all
    // tile-base rows are multiples of 8 with even row>>2)
    int liA = lane & 15, hbA = lane >> 4;
    uint32_t loffA = (uint32_t)(liA * 32 + ((hbA ^ ((liA >> 2) & 1)) << 4));
    int liB = (lane & 7) + ((lane >> 4) << 3);
    int hbB = (lane >> 3) & 1;
    uint32_t loffB = (uint32_t)(liB * 32 + ((hbB ^ ((liB >> 2) & 1)) << 4));

    for (int kt = 0; kt < KT; kt++) {
        cp_wait<STAGES - 2>();
        __syncthreads();
        int nk = kt + STAGES - 1;
        if (nk < KT) issue(nk, nk % STAGES);
        cp_commit();

        int buf = kt % STAGES;
        uint32_t smb = (uint32_t)__cvta_generic_to_shared(sm + buf * STAGE_ELEMS);
        uint32_t Ahb = smb,            Alb = smb + 4096;
        uint32_t Bhb = smb + 8192,     Blb = smb + 8192 + BN * 32;

        uint32_t bh[NT][2], bl[NT][2];
#pragma unroll
        for (int p = 0; p < NT / 2; p++) {
            uint32_t ro = (uint32_t)(wn * (8 * NT) + p * 16) * 32;
            ldsm_x4(&bh[2 * p][0], Bhb + ro + loffB);
            ldsm_x4(&bl[2 * p][0], Blb + ro + loffB);
        }
        if (NT & 1) {
            uint32_t ro = (uint32_t)(wn * (8 * NT) + (NT - 1) * 8) * 32;
            ldsm_x2(&bh[NT - 1][0], Bhb + ro + loffB);
            ldsm_x2(&bl[NT - 1][0], Blb + ro + loffB);
        }

        uint32_t af[4][4];
        // A-hi products
#pragma unroll
        for (int mt = 0; mt < 4; mt++)
            ldsm_x4(af[mt], Ahb + (uint32_t)(wm * 64 + mt * 16) * 32 + loffA);
#pragma unroll
        for (int mt = 0; mt < 4; mt++)
#pragma unroll
            for (int nt = 0; nt < NT; nt++) {
                mma16816(acc[mt][nt], af[mt], bh[nt]);
                mma16816(acc[mt][nt], af[mt], bl[nt]);
            }
        // A-lo product (reuse af registers)
#pragma unroll
        for (int mt = 0; mt < 4; mt++)
            ldsm_x4(af[mt], Alb + (uint32_t)(wm * 64 + mt * 16) * 32 + loffA);
#pragma unroll
        for (int mt = 0; mt < 4; mt++)
#pragma unroll
            for (int nt = 0; nt < NT; nt++)
                mma16816(acc[mt][nt], af[mt], bh[nt]);
        // no trailing __syncthreads: top-of-iteration barrier orders buffer reuse
    }

    // epilogue
#pragma unroll
    for (int mt = 0; mt < 4; mt++)
#pragma unroll
        for (int nt = 0; nt < NT; nt++) {
            int r0 = rb * 128 + wm * 64 + mt * 16 + (lane >> 2);
            int c0 = cb * BN + wn * (8 * NT) + nt * 8 + (lane & 3) * 2;
            float *cc = acc[mt][nt];
            if (SPLIT) {
                float b0 = bias[c0], b1 = bias[c0 + 1];
                if (r0 < NN) {
                    float v0 = fmaxf(cc[0] + b0, 0.f), v1 = fmaxf(cc[1] + b1, 0.f);
                    bf16 h0, l0, h1, l1;
                    fsplit(v0, h0, l0); fsplit(v1, h1, l1);
                    *(bf162 *)(Chi + (size_t)r0 * CHID + c0) = __halves2bfloat162(h0, h1);
                    *(bf162 *)(Clo + (size_t)r0 * CHID + c0) = __halves2bfloat162(l0, l1);
                }
                if (r0 + 8 < NN) {
                    float v0 = fmaxf(cc[2] + b0, 0.f), v1 = fmaxf(cc[3] + b1, 0.f);
                    bf16 h0, l0, h1, l1;
                    fsplit(v0, h0, l0); fsplit(v1, h1, l1);
                    *(bf162 *)(Chi + (size_t)(r0 + 8) * CHID + c0) = __halves2bfloat162(h0, h1);
                    *(bf162 *)(Clo + (size_t)(r0 + 8) * CHID + c0) = __halves2bfloat162(l0, l1);
                }
            } else {
                if (r0 < NN) {
                    if (c0 < NOUT)     Cf[(size_t)r0 * NOUT + c0]     = cc[0];
                    if (c0 + 1 < NOUT) Cf[(size_t)r0 * NOUT + c0 + 1] = cc[1];
                }
                if (r0 + 8 < NN) {
                    if (c0 < NOUT)     Cf[(size_t)(r0 + 8) * NOUT + c0]     = cc[2];
                    if (c0 + 1 < NOUT) Cf[(size_t)(r0 + 8) * NOUT + c0 + 1] = cc[3];
                }
            }
        }
}

// ---------------- fused layer-3 tail: agg(d=40) + self + bias + log_softmax ----------------
__global__ void k_final(const float *__restrict__ b3, float *__restrict__ out) {
    int w = threadIdx.x >> 5, lane = threadIdx.x & 31;
    int node = blockIdx.x * 8 + w;
    if (node >= NN) return;
    int e0 = g_rowptr[node], e1 = g_rowptr[node + 1];
    float a0 = 0.f, a1 = 0.f;
    for (int e = e0; e < e1; e++) {
        int2  pk = g_cpack[e];
        float wt = __int_as_float(pk.y);
        const float *pb = g_p3 + (size_t)pk.x * P3W + COUT;
        a0 += wt * pb[lane];
        if (lane < 8) a1 += wt * pb[32 + lane];
    }
    const float *ps = g_p3 + (size_t)node * P3W;
    float v1 = ps[lane] + a0 + b3[lane];
    float v2 = (lane < 8) ? ps[32 + lane] + a1 + b3[32 + lane] : -INFINITY;
    float m = fmaxf(v1, v2);
#pragma unroll
    for (int o = 16; o; o >>= 1) m = fmaxf(m, __shfl_xor_sync(0xffffffffu, m, o));
    float s = expf(v1 - m) + ((lane < 8) ? expf(v2 - m) : 0.f);
#pragma unroll
    for (int o = 16; o; o >>= 1) s += __shfl_xor_sync(0xffffffffu, s, o);
    float lse = m + logf(s);
    out[(size_t)node * COUT + lane] = v1 - lse;
    if (lane < 8) out[(size_t)node * COUT + 32 + lane] = v2 - lse;
}

// ---------------- launch ----------------
#define SYM(p, s) cudaGetSymbolAddress((void **)&(p), s)

extern "C" void kernel_launch(void *const *d_in, const int *in_sizes, int n_in,
                              void *d_out, int out_size) {
    const float *x  = (const float *)d_in[0];
    const int   *ei = (const int *)d_in[1];
    const float *ew = (const float *)d_in[2];
    const float *W1 = (const float *)d_in[3];
    const float *b1 = (const float *)d_in[4];
    const float *W2 = (const float *)d_in[5];
    const float *b2 = (const float *)d_in[6];
    const float *W3 = (const float *)d_in[7];
    const float *b3 = (const float *)d_in[8];
    float *out = (float *)d_out;
    const int *src = ei;
    const int *dst = ei + NE;

    bf16 *xhi, *xlo, *h1hi, *h1lo, *h2hi, *h2lo, *aghi, *aglo;
    bf16 *w1hi, *w1lo, *w2hi, *w2lo, *w3hi, *w3lo;
    float *p3;
    SYM(xhi, g_xhi);   SYM(xlo, g_xlo);
    SYM(h1hi, g_h1hi); SYM(h1lo, g_h1lo);
    SYM(h2hi, g_h2hi); SYM(h2lo, g_h2lo);
    SYM(aghi, g_aghi); SYM(aglo, g_aglo);
    SYM(w1hi, g_w1hi); SYM(w1lo, g_w1lo);
    SYM(w2hi, g_w2hi); SYM(w2lo, g_w2lo);
    SYM(w3hi, g_w3hi); SYM(w3lo, g_w3lo);
    SYM(p3, g_p3);

    // dynamic smem sizes: STAGES * 2*(128+BN)*16 bf16 elems * 2B
    const int SM_HID = STAGES * 2 * (128 + 256) * 16 * 2;  // NT=8 -> 73728 B
    const int SM_P3  = STAGES * 2 * (128 + 96) * 16 * 2;   // NT=3 -> 43008 B
    cudaFuncSetAttribute(k_gemm<256, CIN, CHID, 8, true>,
                         cudaFuncAttributeMaxDynamicSharedMemorySize, SM_HID);
    cudaFuncSetAttribute(k_gemm<512, CHID, CHID, 8, true>,
                         cudaFuncAttributeMaxDynamicSharedMemorySize, SM_HID);
    cudaFuncSetAttribute(k_gemm<256, 256, P3W, 3, false>,
                         cudaFuncAttributeMaxDynamicSharedMemorySize, SM_P3);

    // CSR build
    k_zero_deg<<<(NN + 255) / 256, 256>>>();
    k_hist<<<(NE + 255) / 256, 256>>>(dst);
    k_scan1<<<SCAN_NB, SCAN_T>>>();
    k_scan2<<<1, 128>>>();
    k_scan3<<<SCAN_NB, SCAN_T>>>();
    k_fill<<<(NE + 255) / 256, 256>>>(src, dst, ew);

    // conversions
    k_split<<<(NN * CIN + 255) / 256, 256>>>(x, xhi, xlo, NN * CIN);
    k_convW<<<(CHID * 2 * CIN + 255) / 256, 256>>>(W1, w1hi, w1lo, 2 * CIN, CHID);
    k_convW<<<(CHID * 2 * CHID + 255) / 256, 256>>>(W2, w2hi, w2lo, 2 * CHID, CHID);
    k_convW3<<<(P3W * CHID + 255) / 256, 256>>>(W3);

    dim3 gHID((NN + 127) / 128, 1);   // full N=256 per CTA
    dim3 gP3((NN + 127) / 128, 1);

    // layer 1
    k_agg128<<<(NN + 7) / 8, 256>>>(x);
    k_gemm<256, CIN, CHID, 8, true><<<gHID, 256, SM_HID>>>(
        xhi, xlo, aghi, aglo, w1hi, w1lo, b1, h1hi, h1lo, nullptr);
    // layer 2
    k_agg256<<<(NN + 7) / 8, 256>>>(h1hi, h1lo);
    k_gemm<512, CHID, CHID, 8, true><<<gHID, 256, SM_HID>>>(
        h1hi, h1lo, aghi, aglo, w2hi, w2lo, b2, h2hi, h2lo, nullptr);
    // layer 3: GEMM first (h2 @ [W3_top|W3_bot] -> P[100k][80]), then fused agg tail
    k_gemm<256, 256, P3W, 3, false><<<gP3, 256, SM_P3>>>(
        h2hi, h2lo, h2hi, h2lo, w3hi, w3lo, nullptr, nullptr, nullptr, p3);
    k_final<<<(NN + 7) / 8, 256>>>(b3, out);
}

// round 13
// speedup vs baseline: 1.0779x; 1.0779x over previous
#include <cuda_runtime.h>
#include <cuda_bf16.h>
#include <stdint.h>
#include <math.h>

#define NN   100000
#define NE   1600000
#define CIN  128
#define CHID 256
#define COUT 40
#define P3W  80          // layer-3 pre-agg width (40 self + 40 agg-input)

typedef __nv_bfloat16  bf16;
typedef __nv_bfloat162 bf162;

#define SCAN_T  1024
#define SCAN_NB ((NN + SCAN_T - 1) / SCAN_T)   // 98

// ---------------- device scratch ----------------
__device__ int   g_deg[NN];
__device__ int   g_rowptr[NN + 1];
__device__ int   g_cursor[NN];
__device__ int   g_bsums[SCAN_NB];
__device__ int2  g_cpack[NE];          // (src, weight bits)

__device__ bf16  g_xhi[(size_t)NN * CIN];
__device__ bf16  g_xlo[(size_t)NN * CIN];
__device__ bf16  g_h1hi[(size_t)NN * CHID];
__device__ bf16  g_h1lo[(size_t)NN * CHID];
__device__ bf16  g_h2hi[(size_t)NN * CHID];
__device__ bf16  g_h2lo[(size_t)NN * CHID];
__device__ bf16  g_aghi[(size_t)NN * CHID];
__device__ bf16  g_aglo[(size_t)NN * CHID];

__device__ bf16  g_w1hi[CHID * 2 * CIN];
__device__ bf16  g_w1lo[CHID * 2 * CIN];
__device__ bf16  g_w2hi[CHID * 2 * CHID];
__device__ bf16  g_w2lo[CHID * 2 * CHID];
__device__ bf16  g_w3hi[P3W * CHID];          // [80][256], k-contiguous (K2=256)
__device__ bf16  g_w3lo[P3W * CHID];

__device__ float g_p3[(size_t)NN * P3W];

// ---------------- helpers ----------------
__device__ __forceinline__ void fsplit(float v, bf16 &hi, bf16 &lo) {
    hi = __float2bfloat16(v);
    lo = __float2bfloat16(v - __bfloat162float(hi));
}

__device__ __forceinline__ void mma16816(float *c, const uint32_t *a, const uint32_t *b) {
    asm volatile(
        "mma.sync.aligned.m16n8k16.row.col.f32.bf16.bf16.f32 "
        "{%0,%1,%2,%3}, {%4,%5,%6,%7}, {%8,%9}, {%0,%1,%2,%3};\n"
        : "+f"(c[0]), "+f"(c[1]), "+f"(c[2]), "+f"(c[3])
        : "r"(a[0]), "r"(a[1]), "r"(a[2]), "r"(a[3]), "r"(b[0]), "r"(b[1]));
}

__device__ __forceinline__ void ldsm_x4(uint32_t *r, uint32_t a) {
    asm volatile("ldmatrix.sync.aligned.m8n8.x4.shared.b16 {%0,%1,%2,%3}, [%4];"
                 : "=r"(r[0]), "=r"(r[1]), "=r"(r[2]), "=r"(r[3]) : "r"(a));
}
__device__ __forceinline__ void ldsm_x2(uint32_t *r, uint32_t a) {
    asm volatile("ldmatrix.sync.aligned.m8n8.x2.shared.b16 {%0,%1}, [%2];"
                 : "=r"(r[0]), "=r"(r[1]) : "r"(a));
}

__device__ __forceinline__ void cp_async16(uint32_t d, const void *s, bool p) {
    asm volatile("cp.async.cg.shared.global [%0], [%1], 16, %2;\n"
                 :: "r"(d), "l"(s), "r"(p ? 16 : 0));
}
__device__ __forceinline__ void cp_commit() { asm volatile("cp.async.commit_group;\n"); }
template <int N> __device__ __forceinline__ void cp_wait() {
    asm volatile("cp.async.wait_group %0;\n" :: "n"(N));
}

// 16B-granular XOR swizzle on 32B rows: conflict-free for both cp.async stores
// and ldmatrix phases.  sw(row, half) = row*32 + ((half ^ ((row>>2)&1)) << 4)
__device__ __forceinline__ uint32_t sw_off(int row, int half) {
    return (uint32_t)(row * 32 + ((half ^ ((row >> 2) & 1)) << 4));
}

// ---------------- CSR build ----------------
__global__ void k_zero_deg() {
    int i = blockIdx.x * blockDim.x + threadIdx.x;
    if (i < NN) g_deg[i] = 0;
}

__global__ void k_hist(const int *__restrict__ dst) {
    int e = blockIdx.x * blockDim.x + threadIdx.x;
    if (e < NE) atomicAdd(&g_deg[dst[e]], 1);
}

__global__ void k_scan1() {
    __shared__ int s[SCAN_T];
    int t = threadIdx.x;
    int g = blockIdx.x * SCAN_T + t;
    int v = (g < NN) ? g_deg[g] : 0;
    s[t] = v;
    __syncthreads();
    for (int o = 1; o < SCAN_T; o <<= 1) {
        int x = (t >= o) ? s[t - o] : 0;
        __syncthreads();
        s[t] += x;
        __syncthreads();
    }
    if (g < NN) g_rowptr[g + 1] = s[t];
    if (t == SCAN_T - 1) g_bsums[blockIdx.x] = s[t];
}

__global__ void k_scan2() {
    __shared__ int s[128];
    int t = threadIdx.x;
    int v = (t < SCAN_NB) ? g_bsums[t] : 0;
    s[t] = v;
    __syncthreads();
    for (int o = 1; o < 128; o <<= 1) {
        int x = (t >= o) ? s[t - o] : 0;
        __syncthreads();
        s[t] += x;
        __syncthreads();
    }
    if (t < SCAN_NB) g_bsums[t] = s[t] - v;
}

__global__ void k_scan3() {
    int g = blockIdx.x * SCAN_T + threadIdx.x;
    if (g < NN) {
        int v = g_rowptr[g + 1] + g_bsums[blockIdx.x];
        g_rowptr[g + 1] = v;
        g_cursor[g] = v - g_deg[g];
    }
    if (g == 0) g_rowptr[0] = 0;
}

__global__ void k_fill(const int *__restrict__ src, const int *__restrict__ dst,
                       const float *__restrict__ ew) {
    int e = blockIdx.x * blockDim.x + threadIdx.x;
    if (e < NE) {
        int d = dst[e];
        int p = atomicAdd(&g_cursor[d], 1);
        g_cpack[p] = make_int2(src[e], __float_as_int(ew[e]));
    }
}

// ---------------- conversions ----------------
__global__ void k_split(const float *__restrict__ in, bf16 *__restrict__ hi,
                        bf16 *__restrict__ lo, int n) {
    int i = blockIdx.x * blockDim.x + threadIdx.x;
    if (i < n) fsplit(in[i], hi[i], lo[i]);
}

__global__ void k_convW(const float *__restrict__ W, bf16 *__restrict__ whi,
                        bf16 *__restrict__ wlo, int K2, int M) {
    int i = blockIdx.x * blockDim.x + threadIdx.x;
    if (i < K2 * M) {
        int n = i / K2;
        int k = i - n * K2;
        fsplit(W[(size_t)k * M + n], whi[i], wlo[i]);
    }
}

// W3 [512][40] fp32 -> B3 [80][256] bf16 hi/lo, k-contiguous with stride CHID=256.
__global__ void k_convW3(const float *__restrict__ W3) {
    int i = blockIdx.x * blockDim.x + threadIdx.x;
    if (i < P3W * CHID) {
        int n = i / CHID;
        int k = i - n * CHID;
        float v = (n < COUT) ? W3[(size_t)k * COUT + n]
                             : W3[(size_t)(CHID + k) * COUT + (n - COUT)];
        fsplit(v, g_w3hi[i], g_w3lo[i]);
    }
}

// ---------------- aggregation (CSR, no atomics) ----------------
union U4 { uint2 u; bf16 b[4]; };
union U8 { uint4 u; bf16 b[8]; };

__global__ void k_agg128(const float *__restrict__ x) {
    int lane = threadIdx.x & 31, w = threadIdx.x >> 5;
    int node = blockIdx.x * 8 + w;
    if (node >= NN) return;
    int e0 = g_rowptr[node], e1 = g_rowptr[node + 1];
    float a0 = 0.f, a1 = 0.f, a2 = 0.f, a3 = 0.f;
    for (int e = e0; e < e1; e++) {
        int2  pk = g_cpack[e];
        float wt = __int_as_float(pk.y);
        float4 v = *(const float4 *)(x + (size_t)pk.x * CIN + lane * 4);
        a0 += wt * v.x; a1 += wt * v.y; a2 += wt * v.z; a3 += wt * v.w;
    }
    U4 oh, ol;
    fsplit(a0, oh.b[0], ol.b[0]);
    fsplit(a1, oh.b[1], ol.b[1]);
    fsplit(a2, oh.b[2], ol.b[2]);
    fsplit(a3, oh.b[3], ol.b[3]);
    size_t off = (size_t)node * CIN + lane * 4;
    *(uint2 *)(g_aghi + off) = oh.u;
    *(uint2 *)(g_aglo + off) = ol.u;
}

__global__ void k_agg256(const bf16 *__restrict__ hhi, const bf16 *__restrict__ hlo) {
    int lane = threadIdx.x & 31, w = threadIdx.x >> 5;
    int node = blockIdx.x * 8 + w;
    if (node >= NN) return;
    int e0 = g_rowptr[node], e1 = g_rowptr[node + 1];
    float acc[8];
#pragma unroll
    for (int j = 0; j < 8; j++) acc[j] = 0.f;
    for (int e = e0; e < e1; e++) {
        int2  pk = g_cpack[e];
        float wt = __int_as_float(pk.y);
        uint4 uh = *(const uint4 *)(hhi + (size_t)pk.x * CHID + lane * 8);
        uint4 ul = *(const uint4 *)(hlo + (size_t)pk.x * CHID + lane * 8);
        const bf162 *ph = (const bf162 *)&uh;
        const bf162 *pl = (const bf162 *)&ul;
#pragma unroll
        for (int j = 0; j < 4; j++) {
            float2 fh = __bfloat1622float2(ph[j]);
            float2 fl = __bfloat1622float2(pl[j]);
            acc[2 * j]     += wt * (fh.x + fl.x);
            acc[2 * j + 1] += wt * (fh.y + fl.y);
        }
    }
    U8 oh, ol;
#pragma unroll
    for (int j = 0; j < 8; j++) fsplit(acc[j], oh.b[j], ol.b[j]);
    size_t off = (size_t)node * CHID + lane * 8;
    *(uint4 *)(g_aghi + off) = oh.u;
    *(uint4 *)(g_aglo + off) = ol.u;
}

// ---------------- GEMM (256 thr, NT<=4, static smem) — round-8 proven config ----------------
// Used for layer 3 (NT=3). Split product: C = Ahi*Bhi + Ahi*Blo + Alo*Bhi
#define STAGES 3

template <int K2, int KPART, int NOUT, int NT, bool SPLIT>
__global__ __launch_bounds__(256, 2) void k_gemm(
    const bf16 *__restrict__ Ah0, const bf16 *__restrict__ Al0,
    const bf16 *__restrict__ Ah1, const bf16 *__restrict__ Al1,
    const bf16 *__restrict__ Bh, const bf16 *__restrict__ Bl,
    const float *__restrict__ bias,
    bf16 *__restrict__ Chi, bf16 *__restrict__ Clo, float *__restrict__ Cf) {

    constexpr int BN = 32 * NT;
    __shared__ bf16 sm[STAGES][2 * (128 + BN) * 16];

    int tid = threadIdx.x, lane = tid & 31, warp = tid >> 5;
    int wm = warp >> 2, wn = warp & 3;            // 2 x 4 warp grid
    int rb = blockIdx.x, cb = blockIdx.y;

    const int KT = K2 / 16;

    float acc[4][NT][4];
#pragma unroll
    for (int a = 0; a < 4; a++)
#pragma unroll
        for (int b = 0; b < NT; b++)
#pragma unroll
            for (int c = 0; c < 4; c++) acc[a][b][c] = 0.f;

    int sr = tid >> 1, sh = tid & 1;
    int a_gr = rb * 128 + sr;
    int b_gn = cb * BN + sr;
    bool a_ok = a_gr < NN;
    bool b_ok = (sr < BN) && (b_gn < NOUT);
    int a_grc = a_ok ? a_gr : 0;
    int b_gnc = b_ok ? b_gn : 0;
    uint32_t st_off = sw_off(sr, sh);

    auto issue = [&](int kt, int buf) {
        int part = (kt * 16 >= KPART) ? 1 : 0;
        int kcol = kt * 16 - part * KPART;
        const bf16 *Ah = part ? Ah1 : Ah0;
        const bf16 *Al = part ? Al1 : Al0;
        uint32_t base = (uint32_t)__cvta_generic_to_shared(&sm[buf][0]);
        cp_async16(base + st_off,        Ah + (size_t)a_grc * KPART + kcol + sh * 8, a_ok);
        cp_async16(base + 4096 + st_off, Al + (size_t)a_grc * KPART + kcol + sh * 8, a_ok);
        if (sr < BN) {
            cp_async16(base + 8192 + st_off,
                       Bh + (size_t)b_gnc * K2 + kt * 16 + sh * 8, b_ok);
            cp_async16(base + 8192 + BN * 32 + st_off,
                       Bl + (size_t)b_gnc * K2 + kt * 16 + sh * 8, b_ok);
        }
    };

#pragma unroll
    for (int s = 0; s < STAGES - 1; s++) {
        issue(s, s);
        cp_commit();
    }

    int liA = lane & 15, hbA = lane >> 4;
    uint32_t loffA = (uint32_t)(liA * 32 + ((hbA ^ ((liA >> 2) & 1)) << 4));
    int liB = (lane & 7) + ((lane >> 4) << 3);
    int hbB = (lane >> 3) & 1;
    uint32_t loffB = (uint32_t)(liB * 32 + ((hbB ^ ((liB >> 2) & 1)) << 4));

    for (int kt = 0; kt < KT; kt++) {
        cp_wait<STAGES - 2>();
        __syncthreads();
        int nk = kt + STAGES - 1;
        if (nk < KT) issue(nk, nk % STAGES);
        cp_commit();

        int buf = kt % STAGES;
        uint32_t smb = (uint32_t)__cvta_generic_to_shared(&sm[buf][0]);
        uint32_t Ahb = smb,            Alb = smb + 4096;
        uint32_t Bhb = smb + 8192,     Blb = smb + 8192 + BN * 32;

        uint32_t bh[NT][2], bl[NT][2];
#pragma unroll
        for (int p = 0; p < NT / 2; p++) {
            uint32_t ro = (uint32_t)(wn * (8 * NT) + p * 16) * 32;
            ldsm_x4(&bh[2 * p][0], Bhb + ro + loffB);
            ldsm_x4(&bl[2 * p][0], Blb + ro + loffB);
        }
        if (NT & 1) {
            uint32_t ro = (uint32_t)(wn * (8 * NT) + (NT - 1) * 8) * 32;
            ldsm_x2(&bh[NT - 1][0], Bhb + ro + loffB);
            ldsm_x2(&bl[NT - 1][0], Blb + ro + loffB);
        }

        uint32_t af[4][4];
#pragma unroll
        for (int mt = 0; mt < 4; mt++)
            ldsm_x4(af[mt], Ahb + (uint32_t)(wm * 64 + mt * 16) * 32 + loffA);
#pragma unroll
        for (int mt = 0; mt < 4; mt++)
#pragma unroll
            for (int nt = 0; nt < NT; nt++) {
                mma16816(acc[mt][nt], af[mt], bh[nt]);
                mma16816(acc[mt][nt], af[mt], bl[nt]);
            }
#pragma unroll
        for (int mt = 0; mt < 4; mt++)
            ldsm_x4(af[mt], Alb + (uint32_t)(wm * 64 + mt * 16) * 32 + loffA);
#pragma unroll
        for (int mt = 0; mt < 4; mt++)
#pragma unroll
            for (int nt = 0; nt < NT; nt++)
                mma16816(acc[mt][nt], af[mt], bh[nt]);
    }

#pragma unroll
    for (int mt = 0; mt < 4; mt++)
#pragma unroll
        for (int nt = 0; nt < NT; nt++) {
            int r0 = rb * 128 + wm * 64 + mt * 16 + (lane >> 2);
            int c0 = cb * BN + wn * (8 * NT) + nt * 8 + (lane & 3) * 2;
            float *cc = acc[mt][nt];
            if (SPLIT) {
                float b0 = bias[c0], b1 = bias[c0 + 1];
                if (r0 < NN) {
                    float v0 = fmaxf(cc[0] + b0, 0.f), v1 = fmaxf(cc[1] + b1, 0.f);
                    bf16 h0, l0, h1, l1;
                    fsplit(v0, h0, l0); fsplit(v1, h1, l1);
                    *(bf162 *)(Chi + (size_t)r0 * CHID + c0) = __halves2bfloat162(h0, h1);
                    *(bf162 *)(Clo + (size_t)r0 * CHID + c0) = __halves2bfloat162(l0, l1);
                }
                if (r0 + 8 < NN) {
                    float v0 = fmaxf(cc[2] + b0, 0.f), v1 = fmaxf(cc[3] + b1, 0.f);
                    bf16 h0, l0, h1, l1;
                    fsplit(v0, h0, l0); fsplit(v1, h1, l1);
                    *(bf162 *)(Chi + (size_t)(r0 + 8) * CHID + c0) = __halves2bfloat162(h0, h1);
                    *(bf162 *)(Clo + (size_t)(r0 + 8) * CHID + c0) = __halves2bfloat162(l0, l1);
                }
            } else {
                if (r0 < NN) {
                    if (c0 < NOUT)     Cf[(size_t)r0 * NOUT + c0]     = cc[0];
                    if (c0 + 1 < NOUT) Cf[(size_t)r0 * NOUT + c0 + 1] = cc[1];
                }
                if (r0 + 8 < NN) {
                    if (c0 < NOUT)     Cf[(size_t)(r0 + 8) * NOUT + c0]     = cc[2];
                    if (c0 + 1 < NOUT) Cf[(size_t)(r0 + 8) * NOUT + c0 + 1] = cc[3];
                }
            }
        }
}

// ---------------- GEMM 512 threads: BM=128, BN=256 in one pass, 16 warps ----------------
// Warp grid 2x8, per-warp tile 64x32 (identical shape to the proven 256-thr NT=4 config).
// A staged once per CTA (halves A L2 traffic vs grid.y=2). NOUT must equal 256.
template <int K2, int KPART>
__global__ __launch_bounds__(512, 1) void k_gemm512(
    const bf16 *__restrict__ Ah0, const bf16 *__restrict__ Al0,
    const bf16 *__restrict__ Ah1, const bf16 *__restrict__ Al1,
    const bf16 *__restrict__ Bh, const bf16 *__restrict__ Bl,
    const float *__restrict__ bias,
    bf16 *__restrict__ Chi, bf16 *__restrict__ Clo) {

    constexpr int BN = 256;
    constexpr int STAGE_ELEMS = 2 * (128 + BN) * 16;   // 12288 bf16 = 24576 B
    extern __shared__ bf16 sm[];                        // [STAGES][STAGE_ELEMS]

    int tid = threadIdx.x, lane = tid & 31, warp = tid >> 5;
    int wm = warp >> 3, wn = warp & 7;            // 2 x 8 warp grid
    int rb = blockIdx.x;

    const int KT = K2 / 16;

    float acc[4][4][4];
#pragma unroll
    for (int a = 0; a < 4; a++)
#pragma unroll
        for (int b = 0; b < 4; b++)
#pragma unroll
            for (int c = 0; c < 4; c++) acc[a][b][c] = 0.f;

    // staging: sr = tid>>1 in [0,256) covers all B rows; sr<128 additionally stages A
    int sr = tid >> 1, sh = tid & 1;
    bool a_stage = sr < 128;
    int a_gr = rb * 128 + sr;
    bool a_ok = a_stage && (a_gr < NN);
    int a_grc = a_ok ? a_gr : 0;
    uint32_t stA = sw_off(sr, sh);
    uint32_t stB = stA;                            // same row index for B

    auto issue = [&](int kt, int buf) {
        int part = (kt * 16 >= KPART) ? 1 : 0;
        int kcol = kt * 16 - part * KPART;
        const bf16 *Ah = part ? Ah1 : Ah0;
        const bf16 *Al = part ? Al1 : Al0;
        uint32_t base = (uint32_t)__cvta_generic_to_shared(sm + buf * STAGE_ELEMS);
        if (a_stage) {
            cp_async16(base + stA,        Ah + (size_t)a_grc * KPART + kcol + sh * 8, a_ok);
            cp_async16(base + 4096 + stA, Al + (size_t)a_grc * KPART + kcol + sh * 8, a_ok);
        }
        // B rows 0..255 == sr; NOUT == 256 so always in-bounds
        cp_async16(base + 8192 + stB,
                   Bh + (size_t)sr * K2 + kt * 16 + sh * 8, true);
        cp_async16(base + 16384 + stB,
                   Bl + (size_t)sr * K2 + kt * 16 + sh * 8, true);
    };

#pragma unroll
    for (int s = 0; s < STAGES - 1; s++) {
        issue(s, s);
        cp_commit();
    }

    int liA = lane & 15, hbA = lane >> 4;
    uint32_t loffA = (uint32_t)(liA * 32 + ((hbA ^ ((liA >> 2) & 1)) << 4));
    int liB = (lane & 7) + ((lane >> 4) << 3);
    int hbB = (lane >> 3) & 1;
    uint32_t loffB = (uint32_t)(liB * 32 + ((hbB ^ ((liB >> 2) & 1)) << 4));

    for (int kt = 0; kt < KT; kt++) {
        cp_wait<STAGES - 2>();
        __syncthreads();
        int nk = kt + STAGES - 1;
        if (nk < KT) issue(nk, nk % STAGES);
        cp_commit();

        int buf = kt % STAGES;
        uint32_t smb = (uint32_t)__cvta_generic_to_shared(sm + buf * STAGE_ELEMS);
        uint32_t Ahb = smb,            Alb = smb + 4096;
        uint32_t Bhb = smb + 8192,     Blb = smb + 16384;

        uint32_t bh[4][2], bl[4][2];
#pragma unroll
        for (int p = 0; p < 2; p++) {
            uint32_t ro = (uint32_t)(wn * 32 + p * 16) * 32;
            ldsm_x4(&bh[2 * p][0], Bhb + ro + loffB);
            ldsm_x4(&bl[2 * p][0], Blb + ro + loffB);
        }

        uint32_t af[4][4];
#pragma unroll
        for (int mt = 0; mt < 4; mt++)
            ldsm_x4(af[mt], Ahb + (uint32_t)(wm * 64 + mt * 16) * 32 + loffA);
#pragma unroll
        for (int mt = 0; mt < 4; mt++)
#pragma unroll
            for (int nt = 0; nt < 4; nt++) {
                mma16816(acc[mt][nt], af[mt], bh[nt]);
                mma16816(acc[mt][nt], af[mt], bl[nt]);
            }
#pragma unroll
        for (int mt = 0; mt < 4; mt++)
            ldsm_x4(af[mt], Alb + (uint32_t)(wm * 64 + mt * 16) * 32 + loffA);
#pragma unroll
        for (int mt = 0; mt < 4; mt++)
#pragma unroll
            for (int nt = 0; nt < 4; nt++)
                mma16816(acc[mt][nt], af[mt], bh[nt]);
    }

    // epilogue (SPLIT path; NOUT == CHID == 256)
#pragma unroll
    for (int mt = 0; mt < 4; mt++)
#pragma unroll
        for (int nt = 0; nt < 4; nt++) {
            int r0 = rb * 128 + wm * 64 + mt * 16 + (lane >> 2);
            int c0 = wn * 32 + nt * 8 + (lane & 3) * 2;
            float *cc = acc[mt][nt];
            float b0 = bias[c0], b1 = bias[c0 + 1];
            if (r0 < NN) {
                float v0 = fmaxf(cc[0] + b0, 0.f), v1 = fmaxf(cc[1] + b1, 0.f);
                bf16 h0, l0, h1, l1;
                fsplit(v0, h0, l0); fsplit(v1, h1, l1);
                *(bf162 *)(Chi + (size_t)r0 * CHID + c0) = __halves2bfloat162(h0, h1);
                *(bf162 *)(Clo + (size_t)r0 * CHID + c0) = __halves2bfloat162(l0, l1);
            }
            if (r0 + 8 < NN) {
                float v0 = fmaxf(cc[2] + b0, 0.f), v1 = fmaxf(cc[3] + b1, 0.f);
                bf16 h0, l0, h1, l1;
                fsplit(v0, h0, l0); fsplit(v1, h1, l1);
                *(bf162 *)(Chi + (size_t)(r0 + 8) * CHID + c0) = __halves2bfloat162(h0, h1);
                *(bf162 *)(Clo + (size_t)(r0 + 8) * CHID + c0) = __halves2bfloat162(l0, l1);
            }
        }
}

// ---------------- fused layer-3 tail: agg(d=40) + self + bias + log_softmax ----------------
__global__ void k_final(const float *__restrict__ b3, float *__restrict__ out) {
    int w = threadIdx.x >> 5, lane = threadIdx.x & 31;
    int node = blockIdx.x * 8 + w;
    if (node >= NN) return;
    int e0 = g_rowptr[node], e1 = g_rowptr[node + 1];
    float a0 = 0.f, a1 = 0.f;
    for (int e = e0; e < e1; e++) {
        int2  pk = g_cpack[e];
        float wt = __int_as_float(pk.y);
        const float *pb = g_p3 + (size_t)pk.x * P3W + COUT;
        a0 += wt * pb[lane];
        if (lane < 8) a1 += wt * pb[32 + lane];
    }
    const float *ps = g_p3 + (size_t)node * P3W;
    float v1 = ps[lane] + a0 + b3[lane];
    float v2 = (lane < 8) ? ps[32 + lane] + a1 + b3[32 + lane] : -INFINITY;
    float m = fmaxf(v1, v2);
#pragma unroll
    for (int o = 16; o; o >>= 1) m = fmaxf(m, __shfl_xor_sync(0xffffffffu, m, o));
    float s = expf(v1 - m) + ((lane < 8) ? expf(v2 - m) : 0.f);
#pragma unroll
    for (int o = 16; o; o >>= 1) s += __shfl_xor_sync(0xffffffffu, s, o);
    float lse = m + logf(s);
    out[(size_t)node * COUT + lane] = v1 - lse;
    if (lane < 8) out[(size_t)node * COUT + 32 + lane] = v2 - lse;
}

// ---------------- launch ----------------
#define SYM(p, s) cudaGetSymbolAddress((void **)&(p), s)

extern "C" void kernel_launch(void *const *d_in, const int *in_sizes, int n_in,
                              void *d_out, int out_size) {
    const float *x  = (const float *)d_in[0];
    const int   *ei = (const int *)d_in[1];
    const float *ew = (const float *)d_in[2];
    const float *W1 = (const float *)d_in[3];
    const float *b1 = (const float *)d_in[4];
    const float *W2 = (const float *)d_in[5];
    const float *b2 = (const float *)d_in[6];
    const float *W3 = (const float *)d_in[7];
    const float *b3 = (const float *)d_in[8];
    float *out = (float *)d_out;
    const int *src = ei;
    const int *dst = ei + NE;

    bf16 *xhi, *xlo, *h1hi, *h1lo, *h2hi, *h2lo, *aghi, *aglo;
    bf16 *w1hi, *w1lo, *w2hi, *w2lo, *w3hi, *w3lo;
    float *p3;
    SYM(xhi, g_xhi);   SYM(xlo, g_xlo);
    SYM(h1hi, g_h1hi); SYM(h1lo, g_h1lo);
    SYM(h2hi, g_h2hi); SYM(h2lo, g_h2lo);
    SYM(aghi, g_aghi); SYM(aglo, g_aglo);
    SYM(w1hi, g_w1hi); SYM(w1lo, g_w1lo);
    SYM(w2hi, g_w2hi); SYM(w2lo, g_w2lo);
    SYM(w3hi, g_w3hi); SYM(w3lo, g_w3lo);
    SYM(p3, g_p3);

    const int SM512 = STAGES * 2 * (128 + 256) * 16 * 2;   // 73728 B
    cudaFuncSetAttribute(k_gemm512<256, CIN>,
                         cudaFuncAttributeMaxDynamicSharedMemorySize, SM512);
    cudaFuncSetAttribute(k_gemm512<512, CHID>,
                         cudaFuncAttributeMaxDynamicSharedMemorySize, SM512);

    // CSR build
    k_zero_deg<<<(NN + 255) / 256, 256>>>();
    k_hist<<<(NE + 255) / 256, 256>>>(dst);
    k_scan1<<<SCAN_NB, SCAN_T>>>();
    k_scan2<<<1, 128>>>();
    k_scan3<<<SCAN_NB, SCAN_T>>>();
    k_fill<<<(NE + 255) / 256, 256>>>(src, dst, ew);

    // conversions
    k_split<<<(NN * CIN + 255) / 256, 256>>>(x, xhi, xlo, NN * CIN);
    k_convW<<<(CHID * 2 * CIN + 255) / 256, 256>>>(W1, w1hi, w1lo, 2 * CIN, CHID);
    k_convW<<<(CHID * 2 * CHID + 255) / 256, 256>>>(W2, w2hi, w2lo, 2 * CHID, CHID);
    k_convW3<<<(P3W * CHID + 255) / 256, 256>>>(W3);

    const int GRID_M = (NN + 127) / 128;   // 782
    dim3 gP3(GRID_M, 1);

    // layer 1
    k_agg128<<<(NN + 7) / 8, 256>>>(x);
    k_gemm512<256, CIN><<<GRID_M, 512, SM512>>>(
        xhi, xlo, aghi, aglo, w1hi, w1lo, b1, h1hi, h1lo);
    // layer 2
    k_agg256<<<(NN + 7) / 8, 256>>>(h1hi, h1lo);
    k_gemm512<512, CHID><<<GRID_M, 512, SM512>>>(
        h1hi, h1lo, aghi, aglo, w2hi, w2lo, b2, h2hi, h2lo);
    // layer 3: GEMM first (h2 @ [W3_top|W3_bot] -> P[100k][80]), then fused agg tail
    k_gemm<256, 256, P3W, 3, false><<<gP3, 256>>>(h2hi, h2lo, h2hi, h2lo, w3hi, w3lo, nullptr,
                                                  nullptr, nullptr, p3);
    k_final<<<(NN + 7) / 8, 256>>>(b3, out);
}

// round 15
// speedup vs baseline: 1.1769x; 1.0918x over previous
#include <cuda_runtime.h>
#include <cuda_bf16.h>
#include <stdint.h>
#include <math.h>

#define NN   100000
#define NE   1600000
#define CIN  128
#define CHID 256
#define COUT 40
#define P3W  80          // layer-3 pre-agg width (40 self + 40 agg-input)

typedef __nv_bfloat16  bf16;
typedef __nv_bfloat162 bf162;

#define SCAN_T  1024
#define SCAN_NB ((NN + SCAN_T - 1) / SCAN_T)   // 98

// ---------------- device scratch ----------------
__device__ int   g_deg[NN];
__device__ int   g_rowptr[NN + 1];
__device__ int   g_cursor[NN];
__device__ int   g_bsums[SCAN_NB];
__device__ int2  g_cpack[NE];          // (src, weight bits)

__device__ bf16  g_xhi[(size_t)NN * CIN];
__device__ bf16  g_xlo[(size_t)NN * CIN];
__device__ bf16  g_h1hi[(size_t)NN * CHID];
__device__ bf16  g_h1lo[(size_t)NN * CHID];
__device__ bf16  g_h2hi[(size_t)NN * CHID];
__device__ bf16  g_h2lo[(size_t)NN * CHID];
__device__ bf16  g_aghi[(size_t)NN * CHID];
__device__ bf16  g_aglo[(size_t)NN * CHID];

__device__ bf16  g_w1hi[CHID * 2 * CIN];
__device__ bf16  g_w1lo[CHID * 2 * CIN];
__device__ bf16  g_w2hi[CHID * 2 * CHID];
__device__ bf16  g_w2lo[CHID * 2 * CHID];
__device__ bf16  g_w3hi[P3W * CHID];          // [80][256], k-contiguous (K2=256)
__device__ bf16  g_w3lo[P3W * CHID];

__device__ float g_p3[(size_t)NN * P3W];

// ---------------- helpers ----------------
__device__ __forceinline__ void fsplit(float v, bf16 &hi, bf16 &lo) {
    hi = __float2bfloat16(v);
    lo = __float2bfloat16(v - __bfloat162float(hi));
}

__device__ __forceinline__ void mma16816(float *c, const uint32_t *a, const uint32_t *b) {
    asm volatile(
        "mma.sync.aligned.m16n8k16.row.col.f32.bf16.bf16.f32 "
        "{%0,%1,%2,%3}, {%4,%5,%6,%7}, {%8,%9}, {%0,%1,%2,%3};\n"
        : "+f"(c[0]), "+f"(c[1]), "+f"(c[2]), "+f"(c[3])
        : "r"(a[0]), "r"(a[1]), "r"(a[2]), "r"(a[3]), "r"(b[0]), "r"(b[1]));
}

__device__ __forceinline__ void ldsm_x4(uint32_t *r, uint32_t a) {
    asm volatile("ldmatrix.sync.aligned.m8n8.x4.shared.b16 {%0,%1,%2,%3}, [%4];"
                 : "=r"(r[0]), "=r"(r[1]), "=r"(r[2]), "=r"(r[3]) : "r"(a));
}
__device__ __forceinline__ void ldsm_x2(uint32_t *r, uint32_t a) {
    asm volatile("ldmatrix.sync.aligned.m8n8.x2.shared.b16 {%0,%1}, [%2];"
                 : "=r"(r[0]), "=r"(r[1]) : "r"(a));
}

__device__ __forceinline__ void cp_async16(uint32_t d, const void *s, bool p) {
    asm volatile("cp.async.cg.shared.global [%0], [%1], 16, %2;\n"
                 :: "r"(d), "l"(s), "r"(p ? 16 : 0));
}
__device__ __forceinline__ void cp_commit() { asm volatile("cp.async.commit_group;\n"); }
template <int N> __device__ __forceinline__ void cp_wait() {
    asm volatile("cp.async.wait_group %0;\n" :: "n"(N));
}

// 16B-granular XOR swizzle on 32B rows: conflict-free for both cp.async stores
// and ldmatrix phases.  sw(row, half) = row*32 + ((half ^ ((row>>2)&1)) << 4)
__device__ __forceinline__ uint32_t sw_off(int row, int half) {
    return (uint32_t)(row * 32 + ((half ^ ((row >> 2) & 1)) << 4));
}

// ---------------- CSR build ----------------
__global__ void k_zero_deg() {
    int i = blockIdx.x * blockDim.x + threadIdx.x;
    if (i < NN) g_deg[i] = 0;
}

__global__ void k_hist(const int *__restrict__ dst) {
    int e = blockIdx.x * blockDim.x + threadIdx.x;
    if (e < NE) atomicAdd(&g_deg[dst[e]], 1);
}

__global__ void k_scan1() {
    __shared__ int s[SCAN_T];
    int t = threadIdx.x;
    int g = blockIdx.x * SCAN_T + t;
    int v = (g < NN) ? g_deg[g] : 0;
    s[t] = v;
    __syncthreads();
    for (int o = 1; o < SCAN_T; o <<= 1) {
        int x = (t >= o) ? s[t - o] : 0;
        __syncthreads();
        s[t] += x;
        __syncthreads();
    }
    if (g < NN) g_rowptr[g + 1] = s[t];
    if (t == SCAN_T - 1) g_bsums[blockIdx.x] = s[t];
}

__global__ void k_scan2() {
    __shared__ int s[128];
    int t = threadIdx.x;
    int v = (t < SCAN_NB) ? g_bsums[t] : 0;
    s[t] = v;
    __syncthreads();
    for (int o = 1; o < 128; o <<= 1) {
        int x = (t >= o) ? s[t - o] : 0;
        __syncthreads();
        s[t] += x;
        __syncthreads();
    }
    if (t < SCAN_NB) g_bsums[t] = s[t] - v;
}

__global__ void k_scan3() {
    int g = blockIdx.x * SCAN_T + threadIdx.x;
    if (g < NN) {
        int v = g_rowptr[g + 1] + g_bsums[blockIdx.x];
        g_rowptr[g + 1] = v;
        g_cursor[g] = v - g_deg[g];
    }
    if (g == 0) g_rowptr[0] = 0;
}

__global__ void k_fill(const int *__restrict__ src, const int *__restrict__ dst,
                       const float *__restrict__ ew) {
    int e = blockIdx.x * blockDim.x + threadIdx.x;
    if (e < NE) {
        int d = dst[e];
        int p = atomicAdd(&g_cursor[d], 1);
        g_cpack[p] = make_int2(src[e], __float_as_int(ew[e]));
    }
}

// ---------------- conversions ----------------
__global__ void k_split(const float *__restrict__ in, bf16 *__restrict__ hi,
                        bf16 *__restrict__ lo, int n) {
    int i = blockIdx.x * blockDim.x + threadIdx.x;
    if (i < n) fsplit(in[i], hi[i], lo[i]);
}

__global__ void k_convW(const float *__restrict__ W, bf16 *__restrict__ whi,
                        bf16 *__restrict__ wlo, int K2, int M) {
    int i = blockIdx.x * blockDim.x + threadIdx.x;
    if (i < K2 * M) {
        int n = i / K2;
        int k = i - n * K2;
        fsplit(W[(size_t)k * M + n], whi[i], wlo[i]);
    }
}

// W3 [512][40] fp32 -> B3 [80][256] bf16 hi/lo, k-contiguous with stride CHID=256.
__global__ void k_convW3(const float *__restrict__ W3) {
    int i = blockIdx.x * blockDim.x + threadIdx.x;
    if (i < P3W * CHID) {
        int n = i / CHID;
        int k = i - n * CHID;
        float v = (n < COUT) ? W3[(size_t)k * COUT + n]
                             : W3[(size_t)(CHID + k) * COUT + (n - COUT)];
        fsplit(v, g_w3hi[i], g_w3lo[i]);
    }
}

// ---------------- aggregation (CSR, no atomics; edge loop unrolled x2 for MLP) ----------------
union U4 { uint2 u; bf16 b[4]; };
union U8 { uint4 u; bf16 b[8]; };

__global__ void k_agg128(const float *__restrict__ x) {
    int lane = threadIdx.x & 31, w = threadIdx.x >> 5;
    int node = blockIdx.x * 8 + w;
    if (node >= NN) return;
    int e0 = g_rowptr[node], e1 = g_rowptr[node + 1];
    float a0 = 0.f, a1 = 0.f, a2 = 0.f, a3 = 0.f;
    int e = e0;
    for (; e + 1 < e1; e += 2) {
        int2  pkA = g_cpack[e];
        int2  pkB = g_cpack[e + 1];
        float4 vA = *(const float4 *)(x + (size_t)pkA.x * CIN + lane * 4);
        float4 vB = *(const float4 *)(x + (size_t)pkB.x * CIN + lane * 4);
        float wA = __int_as_float(pkA.y);
        float wB = __int_as_float(pkB.y);
        a0 += wA * vA.x; a1 += wA * vA.y; a2 += wA * vA.z; a3 += wA * vA.w;
        a0 += wB * vB.x; a1 += wB * vB.y; a2 += wB * vB.z; a3 += wB * vB.w;
    }
    if (e < e1) {
        int2  pk = g_cpack[e];
        float wt = __int_as_float(pk.y);
        float4 v = *(const float4 *)(x + (size_t)pk.x * CIN + lane * 4);
        a0 += wt * v.x; a1 += wt * v.y; a2 += wt * v.z; a3 += wt * v.w;
    }
    U4 oh, ol;
    fsplit(a0, oh.b[0], ol.b[0]);
    fsplit(a1, oh.b[1], ol.b[1]);
    fsplit(a2, oh.b[2], ol.b[2]);
    fsplit(a3, oh.b[3], ol.b[3]);
    size_t off = (size_t)node * CIN + lane * 4;
    *(uint2 *)(g_aghi + off) = oh.u;
    *(uint2 *)(g_aglo + off) = ol.u;
}

__device__ __forceinline__ void acc8(float *acc, float wt, const uint4 &uh, const uint4 &ul) {
    const bf162 *ph = (const bf162 *)&uh;
    const bf162 *pl = (const bf162 *)&ul;
#pragma unroll
    for (int j = 0; j < 4; j++) {
        float2 fh = __bfloat1622float2(ph[j]);
        float2 fl = __bfloat1622float2(pl[j]);
        acc[2 * j]     += wt * (fh.x + fl.x);
        acc[2 * j + 1] += wt * (fh.y + fl.y);
    }
}

__global__ void k_agg256(const bf16 *__restrict__ hhi, const bf16 *__restrict__ hlo) {
    int lane = threadIdx.x & 31, w = threadIdx.x >> 5;
    int node = blockIdx.x * 8 + w;
    if (node >= NN) return;
    int e0 = g_rowptr[node], e1 = g_rowptr[node + 1];
    float acc[8];
#pragma unroll
    for (int j = 0; j < 8; j++) acc[j] = 0.f;
    int e = e0;
    for (; e + 1 < e1; e += 2) {
        int2  pkA = g_cpack[e];
        int2  pkB = g_cpack[e + 1];
        uint4 uhA = *(const uint4 *)(hhi + (size_t)pkA.x * CHID + lane * 8);
        uint4 ulA = *(const uint4 *)(hlo + (size_t)pkA.x * CHID + lane * 8);
        uint4 uhB = *(const uint4 *)(hhi + (size_t)pkB.x * CHID + lane * 8);
        uint4 ulB = *(const uint4 *)(hlo + (size_t)pkB.x * CHID + lane * 8);
        acc8(acc, __int_as_float(pkA.y), uhA, ulA);
        acc8(acc, __int_as_float(pkB.y), uhB, ulB);
    }
    if (e < e1) {
        int2  pk = g_cpack[e];
        uint4 uh = *(const uint4 *)(hhi + (size_t)pk.x * CHID + lane * 8);
        uint4 ul = *(const uint4 *)(hlo + (size_t)pk.x * CHID + lane * 8);
        acc8(acc, __int_as_float(pk.y), uh, ul);
    }
    U8 oh, ol;
#pragma unroll
    for (int j = 0; j < 8; j++) fsplit(acc[j], oh.b[j], ol.b[j]);
    size_t off = (size_t)node * CHID + lane * 8;
    *(uint4 *)(g_aghi + off) = oh.u;
    *(uint4 *)(g_aglo + off) = ol.u;
}

// ---------------- GEMM: 128 x (32*NT) block tile, 8 warps, 3-stage cp.async ----------------
// Round-8 proven config: 256 threads, occ 2, static smem, warp grid 2x4.
// Split product: C = Ahi*Bhi + Ahi*Blo + Alo*Bhi  (fp32 accum)
#define STAGES 3

template <int K2, int KPART, int NOUT, int NT, bool SPLIT>
__global__ __launch_bounds__(256, 2) void k_gemm(
    const bf16 *__restrict__ Ah0, const bf16 *__restrict__ Al0,
    const bf16 *__restrict__ Ah1, const bf16 *__restrict__ Al1,
    const bf16 *__restrict__ Bh, const bf16 *__restrict__ Bl,
    const float *__restrict__ bias,
    bf16 *__restrict__ Chi, bf16 *__restrict__ Clo, float *__restrict__ Cf) {

    constexpr int BN = 32 * NT;
    __shared__ bf16 sm[STAGES][2 * (128 + BN) * 16];

    int tid = threadIdx.x, lane = tid & 31, warp = tid >> 5;
    int wm = warp >> 2, wn = warp & 3;            // 2 x 4 warp grid
    int rb = blockIdx.x, cb = blockIdx.y;

    const int KT = K2 / 16;

    float acc[4][NT][4];
#pragma unroll
    for (int a = 0; a < 4; a++)
#pragma unroll
        for (int b = 0; b < NT; b++)
#pragma unroll
            for (int c = 0; c < 4; c++) acc[a][b][c] = 0.f;

    int sr = tid >> 1, sh = tid & 1;
    int a_gr = rb * 128 + sr;
    int b_gn = cb * BN + sr;
    bool a_ok = a_gr < NN;
    bool b_ok = (sr < BN) && (b_gn < NOUT);
    int a_grc = a_ok ? a_gr : 0;
    int b_gnc = b_ok ? b_gn : 0;
    uint32_t st_off = sw_off(sr, sh);

    auto issue = [&](int kt, int buf) {
        int part = (kt * 16 >= KPART) ? 1 : 0;
        int kcol = kt * 16 - part * KPART;
        const bf16 *Ah = part ? Ah1 : Ah0;
        const bf16 *Al = part ? Al1 : Al0;
        uint32_t base = (uint32_t)__cvta_generic_to_shared(&sm[buf][0]);
        cp_async16(base + st_off,        Ah + (size_t)a_grc * KPART + kcol + sh * 8, a_ok);
        cp_async16(base + 4096 + st_off, Al + (size_t)a_grc * KPART + kcol + sh * 8, a_ok);
        if (sr < BN) {
            cp_async16(base + 8192 + st_off,
                       Bh + (size_t)b_gnc * K2 + kt * 16 + sh * 8, b_ok);
            cp_async16(base + 8192 + BN * 32 + st_off,
                       Bl + (size_t)b_gnc * K2 + kt * 16 + sh * 8, b_ok);
        }
    };

#pragma unroll
    for (int s = 0; s < STAGES - 1; s++) {
        issue(s, s);
        cp_commit();
    }

    int liA = lane & 15, hbA = lane >> 4;
    uint32_t loffA = (uint32_t)(liA * 32 + ((hbA ^ ((liA >> 2) & 1)) << 4));
    int liB = (lane & 7) + ((lane >> 4) << 3);
    int hbB = (lane >> 3) & 1;
    uint32_t loffB = (uint32_t)(liB * 32 + ((hbB ^ ((liB >> 2) & 1)) << 4));

    for (int kt = 0; kt < KT; kt++) {
        cp_wait<STAGES - 2>();
        __syncthreads();
        int nk = kt + STAGES - 1;
        if (nk < KT) issue(nk, nk % STAGES);
        cp_commit();

        int buf = kt % STAGES;
        uint32_t smb = (uint32_t)__cvta_generic_to_shared(&sm[buf][0]);
        uint32_t Ahb = smb,            Alb = smb + 4096;
        uint32_t Bhb = smb + 8192,     Blb = smb + 8192 + BN * 32;

        uint32_t bh[NT][2], bl[NT][2];
#pragma unroll
        for (int p = 0; p < NT / 2; p++) {
            uint32_t ro = (uint32_t)(wn * (8 * NT) + p * 16) * 32;
            ldsm_x4(&bh[2 * p][0], Bhb + ro + loffB);
            ldsm_x4(&bl[2 * p][0], Blb + ro + loffB);
        }
        if (NT & 1) {
            uint32_t ro = (uint32_t)(wn * (8 * NT) + (NT - 1) * 8) * 32;
            ldsm_x2(&bh[NT - 1][0], Bhb + ro + loffB);
            ldsm_x2(&bl[NT - 1][0], Blb + ro + loffB);
        }

        uint32_t af[4][4];
#pragma unroll
        for (int mt = 0; mt < 4; mt++)
            ldsm_x4(af[mt], Ahb + (uint32_t)(wm * 64 + mt * 16) * 32 + loffA);
#pragma unroll
        for (int mt = 0; mt < 4; mt++)
#pragma unroll
            for (int nt = 0; nt < NT; nt++) {
                mma16816(acc[mt][nt], af[mt], bh[nt]);
                mma16816(acc[mt][nt], af[mt], bl[nt]);
            }
#pragma unroll
        for (int mt = 0; mt < 4; mt++)
            ldsm_x4(af[mt], Alb + (uint32_t)(wm * 64 + mt * 16) * 32 + loffA);
#pragma unroll
        for (int mt = 0; mt < 4; mt++)
#pragma unroll
            for (int nt = 0; nt < NT; nt++)
                mma16816(acc[mt][nt], af[mt], bh[nt]);
    }

#pragma unroll
    for (int mt = 0; mt < 4; mt++)
#pragma unroll
        for (int nt = 0; nt < NT; nt++) {
            int r0 = rb * 128 + wm * 64 + mt * 16 + (lane >> 2);
            int c0 = cb * BN + wn * (8 * NT) + nt * 8 + (lane & 3) * 2;
            float *cc = acc[mt][nt];
            if (SPLIT) {
                float b0 = bias[c0], b1 = bias[c0 + 1];
                if (r0 < NN) {
                    float v0 = fmaxf(cc[0] + b0, 0.f), v1 = fmaxf(cc[1] + b1, 0.f);
                    bf16 h0, l0, h1, l1;
                    fsplit(v0, h0, l0); fsplit(v1, h1, l1);
                    *(bf162 *)(Chi + (size_t)r0 * CHID + c0) = __halves2bfloat162(h0, h1);
                    *(bf162 *)(Clo + (size_t)r0 * CHID + c0) = __halves2bfloat162(l0, l1);
                }
                if (r0 + 8 < NN) {
                    float v0 = fmaxf(cc[2] + b0, 0.f), v1 = fmaxf(cc[3] + b1, 0.f);
                    bf16 h0, l0, h1, l1;
                    fsplit(v0, h0, l0); fsplit(v1, h1, l1);
                    *(bf162 *)(Chi + (size_t)(r0 + 8) * CHID + c0) = __halves2bfloat162(h0, h1);
                    *(bf162 *)(Clo + (size_t)(r0 + 8) * CHID + c0) = __halves2bfloat162(l0, l1);
                }
            } else {
                if (r0 < NN) {
                    if (c0 < NOUT)     Cf[(size_t)r0 * NOUT + c0]     = cc[0];
                    if (c0 + 1 < NOUT) Cf[(size_t)r0 * NOUT + c0 + 1] = cc[1];
                }
                if (r0 + 8 < NN) {
                    if (c0 < NOUT)     Cf[(size_t)(r0 + 8) * NOUT + c0]     = cc[2];
                    if (c0 + 1 < NOUT) Cf[(size_t)(r0 + 8) * NOUT + c0 + 1] = cc[3];
                }
            }
        }
}

// ---------------- fused layer-3 tail: agg(d=40) + self + bias + log_softmax ----------------
__global__ void k_final(const float *__restrict__ b3, float *__restrict__ out) {
    int w = threadIdx.x >> 5, lane = threadIdx.x & 31;
    int node = blockIdx.x * 8 + w;
    if (node >= NN) return;
    int e0 = g_rowptr[node], e1 = g_rowptr[node + 1];
    float a0 = 0.f, a1 = 0.f;
    int e = e0;
    for (; e + 1 < e1; e += 2) {
        int2  pkA = g_cpack[e];
        int2  pkB = g_cpack[e + 1];
        const float *pbA = g_p3 + (size_t)pkA.x * P3W + COUT;
        const float *pbB = g_p3 + (size_t)pkB.x * P3W + COUT;
        float vA0 = pbA[lane];
        float vB0 = pbB[lane];
        float vA1 = (lane < 8) ? pbA[32 + lane] : 0.f;
        float vB1 = (lane < 8) ? pbB[32 + lane] : 0.f;
        float wA = __int_as_float(pkA.y);
        float wB = __int_as_float(pkB.y);
        a0 += wA * vA0; if (lane < 8) a1 += wA * vA1;
        a0 += wB * vB0; if (lane < 8) a1 += wB * vB1;
    }
    if (e < e1) {
        int2  pk = g_cpack[e];
        float wt = __int_as_float(pk.y);
        const float *pb = g_p3 + (size_t)pk.x * P3W + COUT;
        a0 += wt * pb[lane];
        if (lane < 8) a1 += wt * pb[32 + lane];
    }
    const float *ps = g_p3 + (size_t)node * P3W;
    float v1 = ps[lane] + a0 + b3[lane];
    float v2 = (lane < 8) ? ps[32 + lane] + a1 + b3[32 + lane] : -INFINITY;
    float m = fmaxf(v1, v2);
#pragma unroll
    for (int o = 16; o; o >>= 1) m = fmaxf(m, __shfl_xor_sync(0xffffffffu, m, o));
    float s = expf(v1 - m) + ((lane < 8) ? expf(v2 - m) : 0.f);
#pragma unroll
    for (int o = 16; o; o >>= 1) s += __shfl_xor_sync(0xffffffffu, s, o);
    float lse = m + logf(s);
    out[(size_t)node * COUT + lane] = v1 - lse;
    if (lane < 8) out[(size_t)node * COUT + 32 + lane] = v2 - lse;
}

// ---------------- launch ----------------
#define SYM(p, s) cudaGetSymbolAddress((void **)&(p), s)

extern "C" void kernel_launch(void *const *d_in, const int *in_sizes, int n_in,
                              void *d_out, int out_size) {
    const float *x  = (const float *)d_in[0];
    const int   *ei = (const int *)d_in[1];
    const float *ew = (const float *)d_in[2];
    const float *W1 = (const float *)d_in[3];
    const float *b1 = (const float *)d_in[4];
    const float *W2 = (const float *)d_in[5];
    const float *b2 = (const float *)d_in[6];
    const float *W3 = (const float *)d_in[7];
    const float *b3 = (const float *)d_in[8];
    float *out = (float *)d_out;
    const int *src = ei;
    const int *dst = ei + NE;

    bf16 *xhi, *xlo, *h1hi, *h1lo, *h2hi, *h2lo, *aghi, *aglo;
    bf16 *w1hi, *w1lo, *w2hi, *w2lo, *w3hi, *w3lo;
    float *p3;
    SYM(xhi, g_xhi);   SYM(xlo, g_xlo);
    SYM(h1hi, g_h1hi); SYM(h1lo, g_h1lo);
    SYM(h2hi, g_h2hi); SYM(h2lo, g_h2lo);
    SYM(aghi, g_aghi); SYM(aglo, g_aglo);
    SYM(w1hi, g_w1hi); SYM(w1lo, g_w1lo);
    SYM(w2hi, g_w2hi); SYM(w2lo, g_w2lo);
    SYM(w3hi, g_w3hi); SYM(w3lo, g_w3lo);
    SYM(p3, g_p3);

    // CSR build
    k_zero_deg<<<(NN + 255) / 256, 256>>>();
    k_hist<<<(NE + 255) / 256, 256>>>(dst);
    k_scan1<<<SCAN_NB, SCAN_T>>>();
    k_scan2<<<1, 128>>>();
    k_scan3<<<SCAN_NB, SCAN_T>>>();
    k_fill<<<(NE + 255) / 256, 256>>>(src, dst, ew);

    // conversions
    k_split<<<(NN * CIN + 255) / 256, 256>>>(x, xhi, xlo, NN * CIN);
    k_convW<<<(CHID * 2 * CIN + 255) / 256, 256>>>(W1, w1hi, w1lo, 2 * CIN, CHID);
    k_convW<<<(CHID * 2 * CHID + 255) / 256, 256>>>(W2, w2hi, w2lo, 2 * CHID, CHID);
    k_convW3<<<(P3W * CHID + 255) / 256, 256>>>(W3);

    dim3 gHID((NN + 127) / 128, 2);
    dim3 gP3((NN + 127) / 128, 1);

    // layer 1
    k_agg128<<<(NN + 7) / 8, 256>>>(x);
    k_gemm<256, CIN, CHID, 4, true><<<gHID, 256>>>(xhi, xlo, aghi, aglo, w1hi, w1lo, b1,
                                                   h1hi, h1lo, nullptr);
    // layer 2
    k_agg256<<<(NN + 7) / 8, 256>>>(h1hi, h1lo);
    k_gemm<512, CHID, CHID, 4, true><<<gHID, 256>>>(h1hi, h1lo, aghi, aglo, w2hi, w2lo, b2,
                                                    h2hi, h2lo, nullptr);
    // layer 3: GEMM first (h2 @ [W3_top|W3_bot] -> P[100k][80]), then fused agg tail
    k_gemm<256, 256, P3W, 3, false><<<gP3, 256>>>(h2hi, h2lo, h2hi, h2lo, w3hi, w3lo, nullptr,
                                                  nullptr, nullptr, p3);
    k_final<<<(NN + 7) / 8, 256>>>(b3, out);
}

// round 16
// speedup vs baseline: 1.2466x; 1.0592x over previous
#include <cuda_runtime.h>
#include <cuda_bf16.h>
#include <stdint.h>
#include <math.h>

#define NN   100000
#define NE   1600000
#define CIN  128
#define CHID 256
#define COUT 40
#define P3W  80          // layer-3 pre-agg width (40 self + 40 agg-input)

typedef __nv_bfloat16  bf16;
typedef __nv_bfloat162 bf162;

#define SCAN_T  1024
#define SCAN_NB ((NN + SCAN_T - 1) / SCAN_T)   // 98

// ---------------- device scratch ----------------
__device__ int   g_deg[NN];
__device__ int   g_rowptr[NN + 1];
__device__ int   g_cursor[NN];
__device__ int   g_bsums[SCAN_NB];
__device__ int2  g_cpack[NE];          // (src, weight bits)

__device__ bf16  g_xhi[(size_t)NN * CIN];
__device__ bf16  g_xlo[(size_t)NN * CIN];
__device__ bf16  g_h1hi[(size_t)NN * CHID];
__device__ bf16  g_h1lo[(size_t)NN * CHID];
__device__ bf16  g_h2hi[(size_t)NN * CHID];
__device__ bf16  g_h2lo[(size_t)NN * CHID];
__device__ bf16  g_aghi[(size_t)NN * CHID];
__device__ bf16  g_aglo[(size_t)NN * CHID];

__device__ bf16  g_w1hi[CHID * 2 * CIN];
__device__ bf16  g_w1lo[CHID * 2 * CIN];
__device__ bf16  g_w2hi[CHID * 2 * CHID];
__device__ bf16  g_w2lo[CHID * 2 * CHID];
__device__ bf16  g_w3hi[P3W * CHID];          // [80][256], k-contiguous (K2=256)
__device__ bf16  g_w3lo[P3W * CHID];

__device__ float g_p3[(size_t)NN * P3W];

#define W1_ELEMS (CHID * 2 * CIN)     // 65536
#define W2_ELEMS (CHID * 2 * CHID)    // 131072
#define W3_ELEMS (P3W * CHID)         // 20480
#define WALL_ELEMS (W1_ELEMS + W2_ELEMS + W3_ELEMS)

// ---------------- helpers ----------------
__device__ __forceinline__ void fsplit(float v, bf16 &hi, bf16 &lo) {
    hi = __float2bfloat16(v);
    lo = __float2bfloat16(v - __bfloat162float(hi));
}

__device__ __forceinline__ void mma16816(float *c, const uint32_t *a, const uint32_t *b) {
    asm volatile(
        "mma.sync.aligned.m16n8k16.row.col.f32.bf16.bf16.f32 "
        "{%0,%1,%2,%3}, {%4,%5,%6,%7}, {%8,%9}, {%0,%1,%2,%3};\n"
        : "+f"(c[0]), "+f"(c[1]), "+f"(c[2]), "+f"(c[3])
        : "r"(a[0]), "r"(a[1]), "r"(a[2]), "r"(a[3]), "r"(b[0]), "r"(b[1]));
}

__device__ __forceinline__ void ldsm_x4(uint32_t *r, uint32_t a) {
    asm volatile("ldmatrix.sync.aligned.m8n8.x4.shared.b16 {%0,%1,%2,%3}, [%4];"
                 : "=r"(r[0]), "=r"(r[1]), "=r"(r[2]), "=r"(r[3]) : "r"(a));
}
__device__ __forceinline__ void ldsm_x2(uint32_t *r, uint32_t a) {
    asm volatile("ldmatrix.sync.aligned.m8n8.x2.shared.b16 {%0,%1}, [%2];"
                 : "=r"(r[0]), "=r"(r[1]) : "r"(a));
}

__device__ __forceinline__ void cp_async16(uint32_t d, const void *s, bool p) {
    asm volatile("cp.async.cg.shared.global [%0], [%1], 16, %2;\n"
                 :: "r"(d), "l"(s), "r"(p ? 16 : 0));
}
__device__ __forceinline__ void cp_commit() { asm volatile("cp.async.commit_group;\n"); }
template <int N> __device__ __forceinline__ void cp_wait() {
    asm volatile("cp.async.wait_group %0;\n" :: "n"(N));
}

// 16B-granular XOR swizzle on 32B rows: conflict-free for both cp.async stores
// and ldmatrix phases.  sw(row, half) = row*32 + ((half ^ ((row>>2)&1)) << 4)
__device__ __forceinline__ uint32_t sw_off(int row, int half) {
    return (uint32_t)(row * 32 + ((half ^ ((row >> 2) & 1)) << 4));
}

// ---------------- CSR build ----------------
__global__ void k_zero_deg() {
    int i = blockIdx.x * blockDim.x + threadIdx.x;
    if (i < NN) g_deg[i] = 0;
}

__global__ void k_hist(const int *__restrict__ dst) {
    int e = blockIdx.x * blockDim.x + threadIdx.x;
    if (e < NE) atomicAdd(&g_deg[dst[e]], 1);
}

__global__ void k_scan1() {
    __shared__ int s[SCAN_T];
    int t = threadIdx.x;
    int g = blockIdx.x * SCAN_T + t;
    int v = (g < NN) ? g_deg[g] : 0;
    s[t] = v;
    __syncthreads();
    for (int o = 1; o < SCAN_T; o <<= 1) {
        int x = (t >= o) ? s[t - o] : 0;
        __syncthreads();
        s[t] += x;
        __syncthreads();
    }
    if (g < NN) g_rowptr[g + 1] = s[t];
    if (t == SCAN_T - 1) g_bsums[blockIdx.x] = s[t];
}

__global__ void k_scan2() {
    __shared__ int s[128];
    int t = threadIdx.x;
    int v = (t < SCAN_NB) ? g_bsums[t] : 0;
    s[t] = v;
    __syncthreads();
    for (int o = 1; o < 128; o <<= 1) {
        int x = (t >= o) ? s[t - o] : 0;
        __syncthreads();
        s[t] += x;
        __syncthreads();
    }
    if (t < SCAN_NB) g_bsums[t] = s[t] - v;
}

__global__ void k_scan3() {
    int g = blockIdx.x * SCAN_T + threadIdx.x;
    if (g < NN) {
        int v = g_rowptr[g + 1] + g_bsums[blockIdx.x];
        g_rowptr[g + 1] = v;
        g_cursor[g] = v - g_deg[g];
    }
    if (g == 0) g_rowptr[0] = 0;
}

__global__ void k_fill(const int *__restrict__ src, const int *__restrict__ dst,
                       const float *__restrict__ ew) {
    int e = blockIdx.x * blockDim.x + threadIdx.x;
    if (e < NE) {
        int d = dst[e];
        int p = atomicAdd(&g_cursor[d], 1);
        g_cpack[p] = make_int2(src[e], __float_as_int(ew[e]));
    }
}

// ---------------- conversions: all three weight matrices in one launch ----------------
__global__ void k_convAll(const float *__restrict__ W1, const float *__restrict__ W2,
                          const float *__restrict__ W3) {
    int i = blockIdx.x * blockDim.x + threadIdx.x;
    if (i < W1_ELEMS) {
        // W1 [256][256] -> B1 [256][256] k-contig
        int n = i / (2 * CIN);
        int k = i - n * (2 * CIN);
        fsplit(W1[(size_t)k * CHID + n], g_w1hi[i], g_w1lo[i]);
    } else if (i < W1_ELEMS + W2_ELEMS) {
        int j = i - W1_ELEMS;
        int n = j / (2 * CHID);
        int k = j - n * (2 * CHID);
        fsplit(W2[(size_t)k * CHID + n], g_w2hi[j], g_w2lo[j]);
    } else if (i < WALL_ELEMS) {
        int j = i - W1_ELEMS - W2_ELEMS;
        int n = j / CHID;
        int k = j - n * CHID;
        float v = (n < COUT) ? W3[(size_t)k * COUT + n]
                             : W3[(size_t)(CHID + k) * COUT + (n - COUT)];
        fsplit(v, g_w3hi[j], g_w3lo[j]);
    }
}

// ---------------- aggregation (CSR, no atomics; x2 unroll; fused x-split) ----------------
union U4 { uint2 u; bf16 b[4]; };
union U8 { uint4 u; bf16 b[8]; };

__global__ void k_agg128(const float *__restrict__ x) {
    int lane = threadIdx.x & 31, w = threadIdx.x >> 5;
    int node = blockIdx.x * 8 + w;
    if (node >= NN) return;
    int e0 = g_rowptr[node], e1 = g_rowptr[node + 1];
    float a0 = 0.f, a1 = 0.f, a2 = 0.f, a3 = 0.f;
    int e = e0;
    for (; e + 1 < e1; e += 2) {
        int2  pkA = g_cpack[e];
        int2  pkB = g_cpack[e + 1];
        float4 vA = *(const float4 *)(x + (size_t)pkA.x * CIN + lane * 4);
        float4 vB = *(const float4 *)(x + (size_t)pkB.x * CIN + lane * 4);
        float wA = __int_as_float(pkA.y);
        float wB = __int_as_float(pkB.y);
        a0 += wA * vA.x; a1 += wA * vA.y; a2 += wA * vA.z; a3 += wA * vA.w;
        a0 += wB * vB.x; a1 += wB * vB.y; a2 += wB * vB.z; a3 += wB * vB.w;
    }
    if (e < e1) {
        int2  pk = g_cpack[e];
        float wt = __int_as_float(pk.y);
        float4 v = *(const float4 *)(x + (size_t)pk.x * CIN + lane * 4);
        a0 += wt * v.x; a1 += wt * v.y; a2 += wt * v.z; a3 += wt * v.w;
    }
    size_t off = (size_t)node * CIN + lane * 4;
    U4 oh, ol;
    fsplit(a0, oh.b[0], ol.b[0]);
    fsplit(a1, oh.b[1], ol.b[1]);
    fsplit(a2, oh.b[2], ol.b[2]);
    fsplit(a3, oh.b[3], ol.b[3]);
    *(uint2 *)(g_aghi + off) = oh.u;
    *(uint2 *)(g_aglo + off) = ol.u;
    // fused self-row split (replaces k_split): x[node] -> xhi/xlo
    float4 sv = *(const float4 *)(x + (size_t)node * CIN + lane * 4);
    fsplit(sv.x, oh.b[0], ol.b[0]);
    fsplit(sv.y, oh.b[1], ol.b[1]);
    fsplit(sv.z, oh.b[2], ol.b[2]);
    fsplit(sv.w, oh.b[3], ol.b[3]);
    *(uint2 *)(g_xhi + off) = oh.u;
    *(uint2 *)(g_xlo + off) = ol.u;
}

__device__ __forceinline__ void acc8(float *acc, float wt, const uint4 &uh, const uint4 &ul) {
    const bf162 *ph = (const bf162 *)&uh;
    const bf162 *pl = (const bf162 *)&ul;
#pragma unroll
    for (int j = 0; j < 4; j++) {
        float2 fh = __bfloat1622float2(ph[j]);
        float2 fl = __bfloat1622float2(pl[j]);
        acc[2 * j]     += wt * (fh.x + fl.x);
        acc[2 * j + 1] += wt * (fh.y + fl.y);
    }
}

__global__ void k_agg256(const bf16 *__restrict__ hhi, const bf16 *__restrict__ hlo) {
    int lane = threadIdx.x & 31, w = threadIdx.x >> 5;
    int node = blockIdx.x * 8 + w;
    if (node >= NN) return;
    int e0 = g_rowptr[node], e1 = g_rowptr[node + 1];
    float acc[8];
#pragma unroll
    for (int j = 0; j < 8; j++) acc[j] = 0.f;
    int e = e0;
    for (; e + 1 < e1; e += 2) {
        int2  pkA = g_cpack[e];
        int2  pkB = g_cpack[e + 1];
        uint4 uhA = *(const uint4 *)(hhi + (size_t)pkA.x * CHID + lane * 8);
        uint4 ulA = *(const uint4 *)(hlo + (size_t)pkA.x * CHID + lane * 8);
        uint4 uhB = *(const uint4 *)(hhi + (size_t)pkB.x * CHID + lane * 8);
        uint4 ulB = *(const uint4 *)(hlo + (size_t)pkB.x * CHID + lane * 8);
        acc8(acc, __int_as_float(pkA.y), uhA, ulA);
        acc8(acc, __int_as_float(pkB.y), uhB, ulB);
    }
    if (e < e1) {
        int2  pk = g_cpack[e];
        uint4 uh = *(const uint4 *)(hhi + (size_t)pk.x * CHID + lane * 8);
        uint4 ul = *(const uint4 *)(hlo + (size_t)pk.x * CHID + lane * 8);
        acc8(acc, __int_as_float(pk.y), uh, ul);
    }
    U8 oh, ol;
#pragma unroll
    for (int j = 0; j < 8; j++) fsplit(acc[j], oh.b[j], ol.b[j]);
    size_t off = (size_t)node * CHID + lane * 8;
    *(uint4 *)(g_aghi + off) = oh.u;
    *(uint4 *)(g_aglo + off) = ol.u;
}

// ---------------- GEMM: 128 x (32*NT) block tile, 8 warps, 3-stage cp.async ----------------
// Round-8 proven config. Grid is (n_col_tiles, n_row_tiles): cb = blockIdx.x varies
// fastest so column-pass CTAs of the same row tile co-run and share A via L2.
#define STAGES 3

template <int K2, int KPART, int NOUT, int NT, bool SPLIT>
__global__ __launch_bounds__(256, 2) void k_gemm(
    const bf16 *__restrict__ Ah0, const bf16 *__restrict__ Al0,
    const bf16 *__restrict__ Ah1, const bf16 *__restrict__ Al1,
    const bf16 *__restrict__ Bh, const bf16 *__restrict__ Bl,
    const float *__restrict__ bias,
    bf16 *__restrict__ Chi, bf16 *__restrict__ Clo, float *__restrict__ Cf) {

    constexpr int BN = 32 * NT;
    __shared__ bf16 sm[STAGES][2 * (128 + BN) * 16];

    int tid = threadIdx.x, lane = tid & 31, warp = tid >> 5;
    int wm = warp >> 2, wn = warp & 3;            // 2 x 4 warp grid
    int cb = blockIdx.x, rb = blockIdx.y;          // cb fastest -> A shared via L2

    const int KT = K2 / 16;

    float acc[4][NT][4];
#pragma unroll
    for (int a = 0; a < 4; a++)
#pragma unroll
        for (int b = 0; b < NT; b++)
#pragma unroll
            for (int c = 0; c < 4; c++) acc[a][b][c] = 0.f;

    int sr = tid >> 1, sh = tid & 1;
    int a_gr = rb * 128 + sr;
    int b_gn = cb * BN + sr;
    bool a_ok = a_gr < NN;
    bool b_ok = (sr < BN) && (b_gn < NOUT);
    int a_grc = a_ok ? a_gr : 0;
    int b_gnc = b_ok ? b_gn : 0;
    uint32_t st_off = sw_off(sr, sh);

    auto issue = [&](int kt, int buf) {
        int part = (kt * 16 >= KPART) ? 1 : 0;
        int kcol = kt * 16 - part * KPART;
        const bf16 *Ah = part ? Ah1 : Ah0;
        const bf16 *Al = part ? Al1 : Al0;
        uint32_t base = (uint32_t)__cvta_generic_to_shared(&sm[buf][0]);
        cp_async16(base + st_off,        Ah + (size_t)a_grc * KPART + kcol + sh * 8, a_ok);
        cp_async16(base + 4096 + st_off, Al + (size_t)a_grc * KPART + kcol + sh * 8, a_ok);
        if (sr < BN) {
            cp_async16(base + 8192 + st_off,
                       Bh + (size_t)b_gnc * K2 + kt * 16 + sh * 8, b_ok);
            cp_async16(base + 8192 + BN * 32 + st_off,
                       Bl + (size_t)b_gnc * K2 + kt * 16 + sh * 8, b_ok);
        }
    };

#pragma unroll
    for (int s = 0; s < STAGES - 1; s++) {
        issue(s, s);
        cp_commit();
    }

    int liA = lane & 15, hbA = lane >> 4;
    uint32_t loffA = (uint32_t)(liA * 32 + ((hbA ^ ((liA >> 2) & 1)) << 4));
    int liB = (lane & 7) + ((lane >> 4) << 3);
    int hbB = (lane >> 3) & 1;
    uint32_t loffB = (uint32_t)(liB * 32 + ((hbB ^ ((liB >> 2) & 1)) << 4));

    for (int kt = 0; kt < KT; kt++) {
        cp_wait<STAGES - 2>();
        __syncthreads();
        int nk = kt + STAGES - 1;
        if (nk < KT) issue(nk, nk % STAGES);
        cp_commit();

        int buf = kt % STAGES;
        uint32_t smb = (uint32_t)__cvta_generic_to_shared(&sm[buf][0]);
        uint32_t Ahb = smb,            Alb = smb + 4096;
        uint32_t Bhb = smb + 8192,     Blb = smb + 8192 + BN * 32;

        uint32_t bh[NT][2], bl[NT][2];
#pragma unroll
        for (int p = 0; p < NT / 2; p++) {
            uint32_t ro = (uint32_t)(wn * (8 * NT) + p * 16) * 32;
            ldsm_x4(&bh[2 * p][0], Bhb + ro + loffB);
            ldsm_x4(&bl[2 * p][0], Blb + ro + loffB);
        }
        if (NT & 1) {
            uint32_t ro = (uint32_t)(wn * (8 * NT) + (NT - 1) * 8) * 32;
            ldsm_x2(&bh[NT - 1][0], Bhb + ro + loffB);
            ldsm_x2(&bl[NT - 1][0], Blb + ro + loffB);
        }

        uint32_t af[4][4];
#pragma unroll
        for (int mt = 0; mt < 4; mt++)
            ldsm_x4(af[mt], Ahb + (uint32_t)(wm * 64 + mt * 16) * 32 + loffA);
#pragma unroll
        for (int mt = 0; mt < 4; mt++)
#pragma unroll
            for (int nt = 0; nt < NT; nt++) {
                mma16816(acc[mt][nt], af[mt], bh[nt]);
                mma16816(acc[mt][nt], af[mt], bl[nt]);
            }
#pragma unroll
        for (int mt = 0; mt < 4; mt++)
            ldsm_x4(af[mt], Alb + (uint32_t)(wm * 64 + mt * 16) * 32 + loffA);
#pragma unroll
        for (int mt = 0; mt < 4; mt++)
#pragma unroll
            for (int nt = 0; nt < NT; nt++)
                mma16816(acc[mt][nt], af[mt], bh[nt]);
    }

#pragma unroll
    for (int mt = 0; mt < 4; mt++)
#pragma unroll
        for (int nt = 0; nt < NT; nt++) {
            int r0 = rb * 128 + wm * 64 + mt * 16 + (lane >> 2);
            int c0 = cb * BN + wn * (8 * NT) + nt * 8 + (lane & 3) * 2;
            float *cc = acc[mt][nt];
            if (SPLIT) {
                float b0 = bias[c0], b1 = bias[c0 + 1];
                if (r0 < NN) {
                    float v0 = fmaxf(cc[0] + b0, 0.f), v1 = fmaxf(cc[1] + b1, 0.f);
                    bf16 h0, l0, h1, l1;
                    fsplit(v0, h0, l0); fsplit(v1, h1, l1);
                    *(bf162 *)(Chi + (size_t)r0 * CHID + c0) = __halves2bfloat162(h0, h1);
                    *(bf162 *)(Clo + (size_t)r0 * CHID + c0) = __halves2bfloat162(l0, l1);
                }
                if (r0 + 8 < NN) {
                    float v0 = fmaxf(cc[2] + b0, 0.f), v1 = fmaxf(cc[3] + b1, 0.f);
                    bf16 h0, l0, h1, l1;
                    fsplit(v0, h0, l0); fsplit(v1, h1, l1);
                    *(bf162 *)(Chi + (size_t)(r0 + 8) * CHID + c0) = __halves2bfloat162(h0, h1);
                    *(bf162 *)(Clo + (size_t)(r0 + 8) * CHID + c0) = __halves2bfloat162(l0, l1);
                }
            } else {
                if (r0 < NN) {
                    if (c0 < NOUT)     Cf[(size_t)r0 * NOUT + c0]     = cc[0];
                    if (c0 + 1 < NOUT) Cf[(size_t)r0 * NOUT + c0 + 1] = cc[1];
                }
                if (r0 + 8 < NN) {
                    if (c0 < NOUT)     Cf[(size_t)(r0 + 8) * NOUT + c0]     = cc[2];
                    if (c0 + 1 < NOUT) Cf[(size_t)(r0 + 8) * NOUT + c0 + 1] = cc[3];
                }
            }
        }
}

// ---------------- fused layer-3 tail: agg(d=40) + self + bias + log_softmax ----------------
__global__ void k_final(const float *__restrict__ b3, float *__restrict__ out) {
    int w = threadIdx.x >> 5, lane = threadIdx.x & 31;
    int node = blockIdx.x * 8 + w;
    if (node >= NN) return;
    int e0 = g_rowptr[node], e1 = g_rowptr[node + 1];
    float a0 = 0.f, a1 = 0.f;
    int e = e0;
    for (; e + 1 < e1; e += 2) {
        int2  pkA = g_cpack[e];
        int2  pkB = g_cpack[e + 1];
        const float *pbA = g_p3 + (size_t)pkA.x * P3W + COUT;
        const float *pbB = g_p3 + (size_t)pkB.x * P3W + COUT;
        float vA0 = pbA[lane];
        float vB0 = pbB[lane];
        float vA1 = (lane < 8) ? pbA[32 + lane] : 0.f;
        float vB1 = (lane < 8) ? pbB[32 + lane] : 0.f;
        float wA = __int_as_float(pkA.y);
        float wB = __int_as_float(pkB.y);
        a0 += wA * vA0; if (lane < 8) a1 += wA * vA1;
        a0 += wB * vB0; if (lane < 8) a1 += wB * vB1;
    }
    if (e < e1) {
        int2  pk = g_cpack[e];
        float wt = __int_as_float(pk.y);
        const float *pb = g_p3 + (size_t)pk.x * P3W + COUT;
        a0 += wt * pb[lane];
        if (lane < 8) a1 += wt * pb[32 + lane];
    }
    const float *ps = g_p3 + (size_t)node * P3W;
    float v1 = ps[lane] + a0 + b3[lane];
    float v2 = (lane < 8) ? ps[32 + lane] + a1 + b3[32 + lane] : -INFINITY;
    float m = fmaxf(v1, v2);
#pragma unroll
    for (int o = 16; o; o >>= 1) m = fmaxf(m, __shfl_xor_sync(0xffffffffu, m, o));
    float s = expf(v1 - m) + ((lane < 8) ? expf(v2 - m) : 0.f);
#pragma unroll
    for (int o = 16; o; o >>= 1) s += __shfl_xor_sync(0xffffffffu, s, o);
    float lse = m + logf(s);
    out[(size_t)node * COUT + lane] = v1 - lse;
    if (lane < 8) out[(size_t)node * COUT + 32 + lane] = v2 - lse;
}

// ---------------- launch ----------------
#define SYM(p, s) cudaGetSymbolAddress((void **)&(p), s)

extern "C" void kernel_launch(void *const *d_in, const int *in_sizes, int n_in,
                              void *d_out, int out_size) {
    const float *x  = (const float *)d_in[0];
    const int   *ei = (const int *)d_in[1];
    const float *ew = (const float *)d_in[2];
    const float *W1 = (const float *)d_in[3];
    const float *b1 = (const float *)d_in[4];
    const float *W2 = (const float *)d_in[5];
    const float *b2 = (const float *)d_in[6];
    const float *W3 = (const float *)d_in[7];
    const float *b3 = (const float *)d_in[8];
    float *out = (float *)d_out;
    const int *src = ei;
    const int *dst = ei + NE;

    bf16 *xhi, *xlo, *h1hi, *h1lo, *h2hi, *h2lo, *aghi, *aglo;
    bf16 *w1hi, *w1lo, *w2hi, *w2lo, *w3hi, *w3lo;
    float *p3;
    SYM(xhi, g_xhi);   SYM(xlo, g_xlo);
    SYM(h1hi, g_h1hi); SYM(h1lo, g_h1lo);
    SYM(h2hi, g_h2hi); SYM(h2lo, g_h2lo);
    SYM(aghi, g_aghi); SYM(aglo, g_aglo);
    SYM(w1hi, g_w1hi); SYM(w1lo, g_w1lo);
    SYM(w2hi, g_w2hi); SYM(w2lo, g_w2lo);
    SYM(w3hi, g_w3hi); SYM(w3lo, g_w3lo);
    SYM(p3, g_p3);

    // CSR build
    k_zero_deg<<<(NN + 255) / 256, 256>>>();
    k_hist<<<(NE + 255) / 256, 256>>>(dst);
    k_scan1<<<SCAN_NB, SCAN_T>>>();
    k_scan2<<<1, 128>>>();
    k_scan3<<<SCAN_NB, SCAN_T>>>();
    k_fill<<<(NE + 255) / 256, 256>>>(src, dst, ew);

    // conversions (weights only; x split fused into k_agg128)
    k_convAll<<<(WALL_ELEMS + 255) / 256, 256>>>(W1, W2, W3);

    const int NR = (NN + 127) / 128;   // 782 row tiles
    dim3 gHID(2, NR);                   // cb fastest: A shared via L2
    dim3 gP3(1, NR);

    // layer 1 (agg128 also produces xhi/xlo)
    k_agg128<<<(NN + 7) / 8, 256>>>(x);
    k_gemm<256, CIN, CHID, 4, true><<<gHID, 256>>>(xhi, xlo, aghi, aglo, w1hi, w1lo, b1,
                                                   h1hi, h1lo, nullptr);
    // layer 2
    k_agg256<<<(NN + 7) / 8, 256>>>(h1hi, h1lo);
    k_gemm<512, CHID, CHID, 4, true><<<gHID, 256>>>(h1hi, h1lo, aghi, aglo, w2hi, w2lo, b2,
                                                    h2hi, h2lo, nullptr);
    // layer 3: GEMM first (h2 @ [W3_top|W3_bot] -> P[100k][80]), then fused agg tail
    k_gemm<256, 256, P3W, 3, false><<<gP3, 256>>>(h2hi, h2lo, h2hi, h2lo, w3hi, w3lo, nullptr,
                                                  nullptr, nullptr, p3);
    k_final<<<(NN + 7) / 8, 256>>>(b3, out);
}